// round 1
// baseline (speedup 1.0000x reference)
#include <cuda_runtime.h>
#include <math.h>

#define B_ 2
#define N_ 4096
#define C_ 768
#define H_ 12
#define D_ 64
#define M_ (B_*N_)
#define SCALE_ 0.125f

// Scratch (allocation-free): Q/K/V in [B,H,N,D], attention out in [B,N,C]
__device__ float g_q[(size_t)B_*H_*N_*D_];
__device__ float g_k[(size_t)B_*H_*N_*D_];
__device__ float g_v[(size_t)B_*H_*N_*D_];
__device__ float g_x[(size_t)M_*C_];

__device__ __forceinline__ float gelu_exact(float x) {
    return 0.5f * x * (1.0f + erff(x * 0.70710678118654752f));
}

// out[m][n] = sum_k X[m][k] * W[n][k]  (+bias, +gelu, optional head-major out)
// BM=BN=128, BK=16, 256 threads, 8x8 per thread
template<int DO_BIAS, int DO_GELU, int HEAD_OUT>
__global__ __launch_bounds__(256, 2)
void proj_kernel(const float* __restrict__ X, const float* __restrict__ W,
                 const float* __restrict__ bias, float* __restrict__ out)
{
    __shared__ float Xs[16][132];
    __shared__ float Ws[16][132];
    const int m0 = blockIdx.y * 128;
    const int n0 = blockIdx.x * 128;
    const int tid = threadIdx.x;
    const int tx = tid & 15, ty = tid >> 4;

    float acc[8][8];
    #pragma unroll
    for (int i = 0; i < 8; i++)
        #pragma unroll
        for (int j = 0; j < 8; j++) acc[i][j] = 0.f;

    for (int k0 = 0; k0 < C_; k0 += 16) {
        #pragma unroll
        for (int u = 0; u < 2; u++) {
            int idx = u * 256 + tid;          // 512 float4 per operand tile
            int row = idx >> 2;               // 0..127
            int c4  = (idx & 3) << 2;         // 0,4,8,12
            float4 xv = *(const float4*)(X + (size_t)(m0 + row) * C_ + k0 + c4);
            Xs[c4+0][row] = xv.x; Xs[c4+1][row] = xv.y;
            Xs[c4+2][row] = xv.z; Xs[c4+3][row] = xv.w;
            float4 wv = *(const float4*)(W + (size_t)(n0 + row) * C_ + k0 + c4);
            Ws[c4+0][row] = wv.x; Ws[c4+1][row] = wv.y;
            Ws[c4+2][row] = wv.z; Ws[c4+3][row] = wv.w;
        }
        __syncthreads();
        #pragma unroll 4
        for (int k = 0; k < 16; k++) {
            float a[8], b[8];
            *(float4*)&a[0] = *(const float4*)&Xs[k][ty * 4];
            *(float4*)&a[4] = *(const float4*)&Xs[k][64 + ty * 4];
            *(float4*)&b[0] = *(const float4*)&Ws[k][tx * 4];
            *(float4*)&b[4] = *(const float4*)&Ws[k][64 + tx * 4];
            #pragma unroll
            for (int i = 0; i < 8; i++)
                #pragma unroll
                for (int j = 0; j < 8; j++)
                    acc[i][j] = fmaf(a[i], b[j], acc[i][j]);
        }
        __syncthreads();
    }

    #pragma unroll
    for (int i = 0; i < 8; i++) {
        int m = m0 + ty * 4 + (i & 3) + ((i >> 2) << 6);
        #pragma unroll
        for (int j = 0; j < 8; j++) {
            int n = n0 + tx * 4 + (j & 3) + ((j >> 2) << 6);
            float v = acc[i][j];
            if (DO_BIAS) v += bias[n];
            if (DO_GELU) v = gelu_exact(v);
            if (HEAD_OUT) {
                int bb = m >> 12;             // N_ = 4096
                int nr = m & (N_ - 1);
                int h  = n >> 6;              // D_ = 64
                int d  = n & 63;
                g_dummy_store:
                ((float*)out)[(((size_t)(bb * H_ + h)) * N_ + nr) * D_ + d] = v;
            } else {
                out[(size_t)m * C_ + n] = v;
            }
        }
    }
}

// Flash attention, fp32. Grid: (N/128, B*H). 256 threads, thread tile 8x4.
__global__ __launch_bounds__(256, 2)
void attn_kernel(float* __restrict__ xout)
{
    extern __shared__ float sm[];
    float (*Qst)[132] = (float(*)[132])sm;                          // [64][132] d-major, pre-scaled
    float (*Kst)[68]  = (float(*)[68])(sm + 64 * 132);              // [64][68]  d-major
    float (*Vs)[68]   = (float(*)[68])(sm + 64 * 132 + 64 * 68);    // [64][68]  key-major
    float (*Ps)[68]   = (float(*)[68])(sm + 64 * 132 + 2 * 64 * 68);// [128][68]

    const int bh = blockIdx.y;
    const int b  = bh / H_, h = bh - b * H_;
    const int q0 = blockIdx.x * 128;
    const int tid = threadIdx.x;
    const int tx = tid & 15, ty = tid >> 4;

    const float* Qg = g_q + ((size_t)bh * N_ + q0) * D_;
    const float* Kg = g_k + (size_t)bh * N_ * D_;
    const float* Vg = g_v + (size_t)bh * N_ * D_;

    // Load Q tile transposed (d-major), folding in the 1/sqrt(D) scale.
    #pragma unroll
    for (int u = 0; u < 8; u++) {
        int idx = u * 256 + tid;              // 2048 float4
        int row = idx >> 4;                   // 0..127
        int d4  = (idx & 15) << 2;
        float4 qv = *(const float4*)(Qg + (size_t)row * D_ + d4);
        Qst[d4+0][row] = qv.x * SCALE_; Qst[d4+1][row] = qv.y * SCALE_;
        Qst[d4+2][row] = qv.z * SCALE_; Qst[d4+3][row] = qv.w * SCALE_;
    }

    float o[8][4];
    float m_run[8], l_run[8];
    #pragma unroll
    for (int i = 0; i < 8; i++) {
        m_run[i] = -1e30f; l_run[i] = 0.f;
        #pragma unroll
        for (int j = 0; j < 4; j++) o[i][j] = 0.f;
    }

    for (int t0 = 0; t0 < N_; t0 += 64) {
        __syncthreads();   // Q visible (1st iter) / Kst,Vs,Ps free for reuse
        #pragma unroll
        for (int u = 0; u < 4; u++) {
            int idx = u * 256 + tid;          // 1024 float4
            int row = idx >> 4;               // 0..63
            int d4  = (idx & 15) << 2;
            float4 kv = *(const float4*)(Kg + (size_t)(t0 + row) * D_ + d4);
            Kst[d4+0][row] = kv.x; Kst[d4+1][row] = kv.y;
            Kst[d4+2][row] = kv.z; Kst[d4+3][row] = kv.w;
            float4 vv = *(const float4*)(Vg + (size_t)(t0 + row) * D_ + d4);
            *(float4*)&Vs[row][d4] = vv;
        }
        __syncthreads();

        // S = (Q*scale) @ K^T : 128x64 tile, thread owns rows ty*8..+7, cols tx*4..+3
        float s[8][4];
        #pragma unroll
        for (int i = 0; i < 8; i++)
            #pragma unroll
            for (int j = 0; j < 4; j++) s[i][j] = 0.f;

        #pragma unroll 8
        for (int d = 0; d < 64; d++) {
            float a[8];
            *(float4*)&a[0] = *(const float4*)&Qst[d][ty * 8];
            *(float4*)&a[4] = *(const float4*)&Qst[d][ty * 8 + 4];
            float4 bv = *(const float4*)&Kst[d][tx * 4];
            #pragma unroll
            for (int i = 0; i < 8; i++) {
                s[i][0] = fmaf(a[i], bv.x, s[i][0]);
                s[i][1] = fmaf(a[i], bv.y, s[i][1]);
                s[i][2] = fmaf(a[i], bv.z, s[i][2]);
                s[i][3] = fmaf(a[i], bv.w, s[i][3]);
            }
        }

        // Online softmax (rows are owned by 16-lane groups sharing ty)
        #pragma unroll
        for (int i = 0; i < 8; i++) {
            float mx = fmaxf(fmaxf(s[i][0], s[i][1]), fmaxf(s[i][2], s[i][3]));
            mx = fmaxf(mx, __shfl_xor_sync(0xffffffffu, mx, 1, 16));
            mx = fmaxf(mx, __shfl_xor_sync(0xffffffffu, mx, 2, 16));
            mx = fmaxf(mx, __shfl_xor_sync(0xffffffffu, mx, 4, 16));
            mx = fmaxf(mx, __shfl_xor_sync(0xffffffffu, mx, 8, 16));
            float mnew = fmaxf(m_run[i], mx);
            float al   = __expf(m_run[i] - mnew);
            m_run[i] = mnew;
            float rs = 0.f;
            #pragma unroll
            for (int j = 0; j < 4; j++) {
                float p = __expf(s[i][j] - mnew);
                s[i][j] = p; rs += p;
            }
            rs += __shfl_xor_sync(0xffffffffu, rs, 1, 16);
            rs += __shfl_xor_sync(0xffffffffu, rs, 2, 16);
            rs += __shfl_xor_sync(0xffffffffu, rs, 4, 16);
            rs += __shfl_xor_sync(0xffffffffu, rs, 8, 16);
            l_run[i] = l_run[i] * al + rs;
            #pragma unroll
            for (int j = 0; j < 4; j++) o[i][j] *= al;
            *(float4*)&Ps[ty * 8 + i][tx * 4] = *(float4*)&s[i][0];
        }
        __syncwarp();   // P rows produced & consumed by the same warp

        // O += P @ V
        #pragma unroll 2
        for (int kk = 0; kk < 64; kk += 4) {
            float4 vb0 = *(const float4*)&Vs[kk + 0][tx * 4];
            float4 vb1 = *(const float4*)&Vs[kk + 1][tx * 4];
            float4 vb2 = *(const float4*)&Vs[kk + 2][tx * 4];
            float4 vb3 = *(const float4*)&Vs[kk + 3][tx * 4];
            #pragma unroll
            for (int i = 0; i < 8; i++) {
                float4 pa = *(const float4*)&Ps[ty * 8 + i][kk];
                o[i][0] = fmaf(pa.x, vb0.x, o[i][0]);
                o[i][0] = fmaf(pa.y, vb1.x, o[i][0]);
                o[i][0] = fmaf(pa.z, vb2.x, o[i][0]);
                o[i][0] = fmaf(pa.w, vb3.x, o[i][0]);
                o[i][1] = fmaf(pa.x, vb0.y, o[i][1]);
                o[i][1] = fmaf(pa.y, vb1.y, o[i][1]);
                o[i][1] = fmaf(pa.z, vb2.y, o[i][1]);
                o[i][1] = fmaf(pa.w, vb3.y, o[i][1]);
                o[i][2] = fmaf(pa.x, vb0.z, o[i][2]);
                o[i][2] = fmaf(pa.y, vb1.z, o[i][2]);
                o[i][2] = fmaf(pa.z, vb2.z, o[i][2]);
                o[i][2] = fmaf(pa.w, vb3.z, o[i][2]);
                o[i][3] = fmaf(pa.x, vb0.w, o[i][3]);
                o[i][3] = fmaf(pa.y, vb1.w, o[i][3]);
                o[i][3] = fmaf(pa.z, vb2.w, o[i][3]);
                o[i][3] = fmaf(pa.w, vb3.w, o[i][3]);
            }
        }
    }

    // Normalize and write to [B,N,C] scratch
    #pragma unroll
    for (int i = 0; i < 8; i++) {
        float inv = 1.f / l_run[i];
        int r = q0 + ty * 8 + i;
        float4 ov = make_float4(o[i][0] * inv, o[i][1] * inv,
                                o[i][2] * inv, o[i][3] * inv);
        *(float4*)(xout + ((size_t)(b * N_ + r)) * C_ + h * D_ + tx * 4) = ov;
    }
}

extern "C" void kernel_launch(void* const* d_in, const int* in_sizes, int n_in,
                              void* d_out, int out_size)
{
    const float* query = (const float*)d_in[0];
    const float* key   = (const float*)d_in[1];
    const float* value = (const float*)d_in[2];
    const float* Wq    = (const float*)d_in[3];
    const float* Wk    = (const float*)d_in[4];
    const float* bk    = (const float*)d_in[5];
    const float* Wv    = (const float*)d_in[6];
    const float* Wp    = (const float*)d_in[7];
    const float* bp    = (const float*)d_in[8];
    float* out = (float*)d_out;

    float *pq, *pk, *pv, *px;
    cudaGetSymbolAddress((void**)&pq, g_q);
    cudaGetSymbolAddress((void**)&pk, g_k);
    cudaGetSymbolAddress((void**)&pv, g_v);
    cudaGetSymbolAddress((void**)&px, g_x);

    dim3 gp(6, 64);   // N tiles x M tiles
    proj_kernel<0, 0, 1><<<gp, 256>>>(query, Wq, nullptr, pq);
    proj_kernel<1, 1, 1><<<gp, 256>>>(key,   Wk, bk,      pk);
    proj_kernel<0, 0, 1><<<gp, 256>>>(value, Wv, nullptr, pv);

    int smem = (64 * 132 + 2 * 64 * 68 + 128 * 68) * (int)sizeof(float); // 103424 B
    cudaFuncSetAttribute(attn_kernel, cudaFuncAttributeMaxDynamicSharedMemorySize, smem);
    attn_kernel<<<dim3(32, 24), 256, smem>>>(px);

    proj_kernel<1, 0, 0><<<gp, 256>>>(px, Wp, bp, out);
}

// round 3
// speedup vs baseline: 1.1696x; 1.1696x over previous
#include <cuda_runtime.h>
#include <cuda_bf16.h>
#include <math.h>
#include <stdint.h>

#define B_ 2
#define N_ 4096
#define C_ 768
#define H_ 12
#define D_ 64
#define M_ (B_*N_)
#define SCALE_ 0.125f

// Scratch (allocation-free): Q/K/V in [B,H,N,D], attention out in [B,N,C]
__device__ float g_q[(size_t)B_*H_*N_*D_];
__device__ float g_k[(size_t)B_*H_*N_*D_];
__device__ float g_v[(size_t)B_*H_*N_*D_];
__device__ float g_x[(size_t)M_*C_];

__device__ __forceinline__ float gelu_exact(float x) {
    return 0.5f * x * (1.0f + erff(x * 0.70710678118654752f));
}

__device__ __forceinline__ uint32_t smem_u32(const void* p) {
    uint32_t a;
    asm("{ .reg .u64 t; cvta.to.shared.u64 t, %1; cvt.u32.u64 %0, t; }" : "=r"(a) : "l"(p));
    return a;
}

// pack two fp32 into bf16x2: low half = a, high half = b (memory order a,b)
#define CVT_BF16X2(res, a, b) \
    asm("cvt.rn.bf16x2.f32 %0, %1, %2;" : "=r"(res) : "f"(b), "f"(a))

#define LDMATRIX_X4(r0, r1, r2, r3, addr) \
    asm volatile("ldmatrix.sync.aligned.m8n8.x4.shared.b16 {%0,%1,%2,%3}, [%4];" \
        : "=r"(r0), "=r"(r1), "=r"(r2), "=r"(r3) : "r"(addr))

#define LDMATRIX_X2(r0, r1, addr) \
    asm volatile("ldmatrix.sync.aligned.m8n8.x2.shared.b16 {%0,%1}, [%2];" \
        : "=r"(r0), "=r"(r1) : "r"(addr))

#define MMA_BF16(d, a, b) \
    asm volatile("mma.sync.aligned.m16n8k16.row.col.f32.bf16.bf16.f32 " \
        "{%0,%1,%2,%3}, {%4,%5,%6,%7}, {%8,%9}, {%0,%1,%2,%3};" \
        : "+f"((d)[0]), "+f"((d)[1]), "+f"((d)[2]), "+f"((d)[3]) \
        : "r"((a)[0]), "r"((a)[1]), "r"((a)[2]), "r"((a)[3]), "r"((b)[0]), "r"((b)[1]))

// ------------------------------------------------------------ HMMA projection
// out[m][n] = sum_k X[m][k]*W[n][k] (+bias, +gelu, optional head-major out)
// Split-bf16 (3 passes: hh + hl + lh). Tile 128x128, BK=32, 256 threads.
// Warp grid 2(M) x 4(N): warp tile 64x32. Smem rows padded to 40 bf16 (80B)
// -> ldmatrix row addresses hit distinct 16B bank groups.
#define PADK 40

template<int DO_BIAS, int DO_GELU, int HEAD_OUT>
__global__ __launch_bounds__(256)
void proj_mma(const float* __restrict__ X, const float* __restrict__ W,
              const float* __restrict__ bias, float* __restrict__ out)
{
    __shared__ __align__(16) __nv_bfloat16 sAhi[128 * PADK];
    __shared__ __align__(16) __nv_bfloat16 sAlo[128 * PADK];
    __shared__ __align__(16) __nv_bfloat16 sBhi[128 * PADK];
    __shared__ __align__(16) __nv_bfloat16 sBlo[128 * PADK];

    const int m0 = blockIdx.y * 128;
    const int n0 = blockIdx.x * 128;
    const int tid = threadIdx.x;
    const int lane = tid & 31;
    const int warp = tid >> 5;
    const int wm = warp & 1;          // 0..1 -> 64 rows
    const int wn = warp >> 1;         // 0..3 -> 32 cols

    float acc[4][4][4];
    #pragma unroll
    for (int i = 0; i < 4; i++)
        #pragma unroll
        for (int j = 0; j < 4; j++)
            #pragma unroll
            for (int e = 0; e < 4; e++) acc[i][j][e] = 0.f;

    // precompute ldmatrix smem addresses (row part varies only with ks offset)
    const uint32_t aRowHi = smem_u32(&sAhi[(wm * 64 + (lane & 15)) * PADK + (lane >> 4) * 8]);
    const uint32_t aRowLo = smem_u32(&sAlo[(wm * 64 + (lane & 15)) * PADK + (lane >> 4) * 8]);
    const uint32_t bRowHi = smem_u32(&sBhi[(wn * 32 + (lane & 7)) * PADK + ((lane >> 3) & 1) * 8]);
    const uint32_t bRowLo = smem_u32(&sBlo[(wn * 32 + (lane & 7)) * PADK + ((lane >> 3) & 1) * 8]);

    for (int kc = 0; kc < C_ / 32; kc++) {
        const int k0 = kc * 32;
        // load fp32, split into hi/lo bf16, store to smem
        #pragma unroll
        for (int u = 0; u < 4; u++) {
            int idx = u * 256 + tid;          // 1024 float4 per operand
            int row = idx >> 3;               // 0..127
            int c4  = idx & 7;                // float4 within 32-float row
            uint32_t h01, h23, l01, l23;

            float4 xv = *(const float4*)(X + (size_t)(m0 + row) * C_ + k0 + c4 * 4);
            CVT_BF16X2(h01, xv.x, xv.y);
            CVT_BF16X2(h23, xv.z, xv.w);
            float r0 = xv.x - __uint_as_float(h01 << 16);
            float r1 = xv.y - __uint_as_float(h01 & 0xffff0000u);
            float r2 = xv.z - __uint_as_float(h23 << 16);
            float r3 = xv.w - __uint_as_float(h23 & 0xffff0000u);
            CVT_BF16X2(l01, r0, r1);
            CVT_BF16X2(l23, r2, r3);
            *(uint2*)&sAhi[row * PADK + c4 * 4] = make_uint2(h01, h23);
            *(uint2*)&sAlo[row * PADK + c4 * 4] = make_uint2(l01, l23);

            float4 wv = *(const float4*)(W + (size_t)(n0 + row) * C_ + k0 + c4 * 4);
            CVT_BF16X2(h01, wv.x, wv.y);
            CVT_BF16X2(h23, wv.z, wv.w);
            r0 = wv.x - __uint_as_float(h01 << 16);
            r1 = wv.y - __uint_as_float(h01 & 0xffff0000u);
            r2 = wv.z - __uint_as_float(h23 << 16);
            r3 = wv.w - __uint_as_float(h23 & 0xffff0000u);
            CVT_BF16X2(l01, r0, r1);
            CVT_BF16X2(l23, r2, r3);
            *(uint2*)&sBhi[row * PADK + c4 * 4] = make_uint2(h01, h23);
            *(uint2*)&sBlo[row * PADK + c4 * 4] = make_uint2(l01, l23);
        }
        __syncthreads();

        #pragma unroll
        for (int ks = 0; ks < 2; ks++) {
            const uint32_t koff = ks * 16 * 2;   // 16 bf16 = 32 bytes
            uint32_t ahi[4][4], alo[4][4], bhi[4][2], blo[4][2];
            #pragma unroll
            for (int mi = 0; mi < 4; mi++) {
                uint32_t ofs = mi * 16 * PADK * 2 + koff;
                LDMATRIX_X4(ahi[mi][0], ahi[mi][1], ahi[mi][2], ahi[mi][3], aRowHi + ofs);
                LDMATRIX_X4(alo[mi][0], alo[mi][1], alo[mi][2], alo[mi][3], aRowLo + ofs);
            }
            #pragma unroll
            for (int ni = 0; ni < 4; ni++) {
                uint32_t ofs = ni * 8 * PADK * 2 + koff;
                LDMATRIX_X2(bhi[ni][0], bhi[ni][1], bRowHi + ofs);
                LDMATRIX_X2(blo[ni][0], blo[ni][1], bRowLo + ofs);
            }
            #pragma unroll
            for (int mi = 0; mi < 4; mi++)
                #pragma unroll
                for (int ni = 0; ni < 4; ni++) {
                    MMA_BF16(acc[mi][ni], ahi[mi], bhi[ni]);
                    MMA_BF16(acc[mi][ni], ahi[mi], blo[ni]);
                    MMA_BF16(acc[mi][ni], alo[mi], bhi[ni]);
                }
        }
        __syncthreads();
    }

    // epilogue: write accumulators (c-frag: rows lane>>2 (+8), cols (lane&3)*2 (+1))
    #pragma unroll
    for (int mi = 0; mi < 4; mi++)
        #pragma unroll
        for (int ni = 0; ni < 4; ni++)
            #pragma unroll
            for (int e = 0; e < 4; e++) {
                int m = m0 + wm * 64 + mi * 16 + (lane >> 2) + (e >> 1) * 8;
                int n = n0 + wn * 32 + ni * 8 + (lane & 3) * 2 + (e & 1);
                float v = acc[mi][ni][e];
                if (DO_BIAS) v += bias[n];
                if (DO_GELU) v = gelu_exact(v);
                if (HEAD_OUT) {
                    int bb = m >> 12, nr = m & (N_ - 1);
                    int h = n >> 6, d = n & 63;
                    out[(((size_t)(bb * H_ + h)) * N_ + nr) * D_ + d] = v;
                } else {
                    out[(size_t)m * C_ + n] = v;
                }
            }
}

// ------------------------------------------------------- flash attention (fp32)
__global__ __launch_bounds__(256, 2)
void attn_kernel(float* __restrict__ xout)
{
    extern __shared__ __align__(16) char dynsm[];
    float* sm = (float*)dynsm;
    float (*Qst)[132] = (float(*)[132])sm;                          // [64][132] d-major, pre-scaled
    float (*Kst)[68]  = (float(*)[68])(sm + 64 * 132);              // [64][68]  d-major
    float (*Vs)[68]   = (float(*)[68])(sm + 64 * 132 + 64 * 68);    // [64][68]  key-major
    float (*Ps)[68]   = (float(*)[68])(sm + 64 * 132 + 2 * 64 * 68);// [128][68]

    const int bh = blockIdx.y;
    const int b  = bh / H_, h = bh - b * H_;
    const int q0 = blockIdx.x * 128;
    const int tid = threadIdx.x;
    const int tx = tid & 15, ty = tid >> 4;

    const float* Qg = g_q + ((size_t)bh * N_ + q0) * D_;
    const float* Kg = g_k + (size_t)bh * N_ * D_;
    const float* Vg = g_v + (size_t)bh * N_ * D_;

    #pragma unroll
    for (int u = 0; u < 8; u++) {
        int idx = u * 256 + tid;
        int row = idx >> 4;
        int d4  = (idx & 15) << 2;
        float4 qv = *(const float4*)(Qg + (size_t)row * D_ + d4);
        Qst[d4+0][row] = qv.x * SCALE_; Qst[d4+1][row] = qv.y * SCALE_;
        Qst[d4+2][row] = qv.z * SCALE_; Qst[d4+3][row] = qv.w * SCALE_;
    }

    float o[8][4];
    float m_run[8], l_run[8];
    #pragma unroll
    for (int i = 0; i < 8; i++) {
        m_run[i] = -1e30f; l_run[i] = 0.f;
        #pragma unroll
        for (int j = 0; j < 4; j++) o[i][j] = 0.f;
    }

    for (int t0 = 0; t0 < N_; t0 += 64) {
        __syncthreads();
        #pragma unroll
        for (int u = 0; u < 4; u++) {
            int idx = u * 256 + tid;
            int row = idx >> 4;
            int d4  = (idx & 15) << 2;
            float4 kv = *(const float4*)(Kg + (size_t)(t0 + row) * D_ + d4);
            Kst[d4+0][row] = kv.x; Kst[d4+1][row] = kv.y;
            Kst[d4+2][row] = kv.z; Kst[d4+3][row] = kv.w;
            float4 vv = *(const float4*)(Vg + (size_t)(t0 + row) * D_ + d4);
            *(float4*)&Vs[row][d4] = vv;
        }
        __syncthreads();

        float s[8][4];
        #pragma unroll
        for (int i = 0; i < 8; i++)
            #pragma unroll
            for (int j = 0; j < 4; j++) s[i][j] = 0.f;

        #pragma unroll 8
        for (int d = 0; d < 64; d++) {
            float a[8];
            *(float4*)&a[0] = *(const float4*)&Qst[d][ty * 8];
            *(float4*)&a[4] = *(const float4*)&Qst[d][ty * 8 + 4];
            float4 bv = *(const float4*)&Kst[d][tx * 4];
            #pragma unroll
            for (int i = 0; i < 8; i++) {
                s[i][0] = fmaf(a[i], bv.x, s[i][0]);
                s[i][1] = fmaf(a[i], bv.y, s[i][1]);
                s[i][2] = fmaf(a[i], bv.z, s[i][2]);
                s[i][3] = fmaf(a[i], bv.w, s[i][3]);
            }
        }

        #pragma unroll
        for (int i = 0; i < 8; i++) {
            float mx = fmaxf(fmaxf(s[i][0], s[i][1]), fmaxf(s[i][2], s[i][3]));
            mx = fmaxf(mx, __shfl_xor_sync(0xffffffffu, mx, 1, 16));
            mx = fmaxf(mx, __shfl_xor_sync(0xffffffffu, mx, 2, 16));
            mx = fmaxf(mx, __shfl_xor_sync(0xffffffffu, mx, 4, 16));
            mx = fmaxf(mx, __shfl_xor_sync(0xffffffffu, mx, 8, 16));
            float mnew = fmaxf(m_run[i], mx);
            float al   = __expf(m_run[i] - mnew);
            m_run[i] = mnew;
            float rs = 0.f;
            #pragma unroll
            for (int j = 0; j < 4; j++) {
                float p = __expf(s[i][j] - mnew);
                s[i][j] = p; rs += p;
            }
            rs += __shfl_xor_sync(0xffffffffu, rs, 1, 16);
            rs += __shfl_xor_sync(0xffffffffu, rs, 2, 16);
            rs += __shfl_xor_sync(0xffffffffu, rs, 4, 16);
            rs += __shfl_xor_sync(0xffffffffu, rs, 8, 16);
            l_run[i] = l_run[i] * al + rs;
            #pragma unroll
            for (int j = 0; j < 4; j++) o[i][j] *= al;
            *(float4*)&Ps[ty * 8 + i][tx * 4] = *(float4*)&s[i][0];
        }
        __syncwarp();

        #pragma unroll 2
        for (int kk = 0; kk < 64; kk += 4) {
            float4 vb0 = *(const float4*)&Vs[kk + 0][tx * 4];
            float4 vb1 = *(const float4*)&Vs[kk + 1][tx * 4];
            float4 vb2 = *(const float4*)&Vs[kk + 2][tx * 4];
            float4 vb3 = *(const float4*)&Vs[kk + 3][tx * 4];
            #pragma unroll
            for (int i = 0; i < 8; i++) {
                float4 pa = *(const float4*)&Ps[ty * 8 + i][kk];
                o[i][0] = fmaf(pa.x, vb0.x, o[i][0]);
                o[i][0] = fmaf(pa.y, vb1.x, o[i][0]);
                o[i][0] = fmaf(pa.z, vb2.x, o[i][0]);
                o[i][0] = fmaf(pa.w, vb3.x, o[i][0]);
                o[i][1] = fmaf(pa.x, vb0.y, o[i][1]);
                o[i][1] = fmaf(pa.y, vb1.y, o[i][1]);
                o[i][1] = fmaf(pa.z, vb2.y, o[i][1]);
                o[i][1] = fmaf(pa.w, vb3.y, o[i][1]);
                o[i][2] = fmaf(pa.x, vb0.z, o[i][2]);
                o[i][2] = fmaf(pa.y, vb1.z, o[i][2]);
                o[i][2] = fmaf(pa.z, vb2.z, o[i][2]);
                o[i][2] = fmaf(pa.w, vb3.z, o[i][2]);
                o[i][3] = fmaf(pa.x, vb0.w, o[i][3]);
                o[i][3] = fmaf(pa.y, vb1.w, o[i][3]);
                o[i][3] = fmaf(pa.z, vb2.w, o[i][3]);
                o[i][3] = fmaf(pa.w, vb3.w, o[i][3]);
            }
        }
    }

    #pragma unroll
    for (int i = 0; i < 8; i++) {
        float inv = 1.f / l_run[i];
        int r = q0 + ty * 8 + i;
        float4 ov = make_float4(o[i][0] * inv, o[i][1] * inv,
                                o[i][2] * inv, o[i][3] * inv);
        *(float4*)(xout + ((size_t)(b * N_ + r)) * C_ + h * D_ + tx * 4) = ov;
    }
}

extern "C" void kernel_launch(void* const* d_in, const int* in_sizes, int n_in,
                              void* d_out, int out_size)
{
    const float* query = (const float*)d_in[0];
    const float* key   = (const float*)d_in[1];
    const float* value = (const float*)d_in[2];
    const float* Wq    = (const float*)d_in[3];
    const float* Wk    = (const float*)d_in[4];
    const float* bk    = (const float*)d_in[5];
    const float* Wv    = (const float*)d_in[6];
    const float* Wp    = (const float*)d_in[7];
    const float* bp    = (const float*)d_in[8];
    float* out = (float*)d_out;

    float *pq, *pk, *pv, *px;
    cudaGetSymbolAddress((void**)&pq, g_q);
    cudaGetSymbolAddress((void**)&pk, g_k);
    cudaGetSymbolAddress((void**)&pv, g_v);
    cudaGetSymbolAddress((void**)&px, g_x);

    dim3 gp(6, 64);   // N tiles x M tiles
    proj_mma<0,0,1><<<gp, 256>>>(query, Wq, nullptr, pq);
    proj_mma<1,1,1><<<gp, 256>>>(key,   Wk, bk,      pk);
    proj_mma<0,0,1><<<gp, 256>>>(value, Wv, nullptr, pv);

    int asmem = (64 * 132 + 2 * 64 * 68 + 128 * 68) * (int)sizeof(float); // 103424 B
    static bool attr_done = false;
    if (!attr_done) {
        cudaFuncSetAttribute(attn_kernel, cudaFuncAttributeMaxDynamicSharedMemorySize, asmem);
        attr_done = true;
    }
    attn_kernel<<<dim3(32, 24), 256, asmem>>>(px);

    proj_mma<1,0,0><<<gp, 256>>>(px, Wp, bp, out);
}

// round 4
// speedup vs baseline: 2.3547x; 2.0132x over previous
#include <cuda_runtime.h>
#include <cuda_bf16.h>
#include <math.h>
#include <stdint.h>

#define B_ 2
#define N_ 4096
#define C_ 768
#define H_ 12
#define D_ 64
#define M_ (B_*N_)
#define SCALE_ 0.125f

// Scratch (allocation-free). Q/K/V stored as split bf16 (hi + lo) in [B,H,N,D].
__device__ __align__(16) __nv_bfloat16 g_qh[(size_t)B_*H_*N_*D_];
__device__ __align__(16) __nv_bfloat16 g_ql[(size_t)B_*H_*N_*D_];
__device__ __align__(16) __nv_bfloat16 g_kh[(size_t)B_*H_*N_*D_];
__device__ __align__(16) __nv_bfloat16 g_kl[(size_t)B_*H_*N_*D_];
__device__ __align__(16) __nv_bfloat16 g_vh[(size_t)B_*H_*N_*D_];
__device__ __align__(16) __nv_bfloat16 g_vl[(size_t)B_*H_*N_*D_];
__device__ __align__(16) float g_x[(size_t)M_*C_];   // attention out [B,N,C]

__device__ __forceinline__ float gelu_exact(float x) {
    return 0.5f * x * (1.0f + erff(x * 0.70710678118654752f));
}

__device__ __forceinline__ uint32_t smem_u32(const void* p) {
    uint32_t a;
    asm("{ .reg .u64 t; cvta.to.shared.u64 t, %1; cvt.u32.u64 %0, t; }" : "=r"(a) : "l"(p));
    return a;
}

// pack two fp32 into bf16x2: low half = a, high half = b (memory order a,b)
#define CVT_BF16X2(res, a, b) \
    asm("cvt.rn.bf16x2.f32 %0, %1, %2;" : "=r"(res) : "f"(b), "f"(a))

#define LDMATRIX_X4(r0, r1, r2, r3, addr) \
    asm volatile("ldmatrix.sync.aligned.m8n8.x4.shared.b16 {%0,%1,%2,%3}, [%4];" \
        : "=r"(r0), "=r"(r1), "=r"(r2), "=r"(r3) : "r"(addr))

#define LDMATRIX_X4_T(r0, r1, r2, r3, addr) \
    asm volatile("ldmatrix.sync.aligned.m8n8.x4.trans.shared.b16 {%0,%1,%2,%3}, [%4];" \
        : "=r"(r0), "=r"(r1), "=r"(r2), "=r"(r3) : "r"(addr))

#define LDMATRIX_X2(r0, r1, addr) \
    asm volatile("ldmatrix.sync.aligned.m8n8.x2.shared.b16 {%0,%1}, [%2];" \
        : "=r"(r0), "=r"(r1) : "r"(addr))

__device__ __forceinline__ void mma16816(float* d, uint32_t a0, uint32_t a1,
                                         uint32_t a2, uint32_t a3,
                                         uint32_t b0, uint32_t b1) {
    asm volatile("mma.sync.aligned.m16n8k16.row.col.f32.bf16.bf16.f32 "
        "{%0,%1,%2,%3}, {%4,%5,%6,%7}, {%8,%9}, {%0,%1,%2,%3};"
        : "+f"(d[0]), "+f"(d[1]), "+f"(d[2]), "+f"(d[3])
        : "r"(a0), "r"(a1), "r"(a2), "r"(a3), "r"(b0), "r"(b1));
}

__device__ __forceinline__ void cp16(uint32_t saddr, const void* g) {
    asm volatile("cp.async.ca.shared.global [%0], [%1], 16;" :: "r"(saddr), "l"(g));
}
#define CP_COMMIT() asm volatile("cp.async.commit_group;" ::: "memory")
#define CP_WAIT(n)  asm volatile("cp.async.wait_group %0;" :: "n"(n) : "memory")

#define MMA_BF16(d, a, b) \
    asm volatile("mma.sync.aligned.m16n8k16.row.col.f32.bf16.bf16.f32 " \
        "{%0,%1,%2,%3}, {%4,%5,%6,%7}, {%8,%9}, {%0,%1,%2,%3};" \
        : "+f"((d)[0]), "+f"((d)[1]), "+f"((d)[2]), "+f"((d)[3]) \
        : "r"((a)[0]), "r"((a)[1]), "r"((a)[2]), "r"((a)[3]), "r"((b)[0]), "r"((b)[1]))

// ------------------------------------------------------------ HMMA projection
// out[m][n] = sum_k X[m][k]*W[n][k] (+bias, +gelu). Split-bf16, 3 passes.
// MODE 0: write fp32 [M][C] to outA.  MODE 1: write split bf16 head-major
// ([B,H,N,D]) to outA(hi)/outB(lo), optional DO_SCALE (Q) pre-split.
#define PADK 40

template<int DO_BIAS, int DO_GELU, int DO_SCALE, int HEAD_OUT>
__global__ __launch_bounds__(256)
void proj_mma(const float* __restrict__ X, const float* __restrict__ W,
              const float* __restrict__ bias,
              float* __restrict__ outF,
              __nv_bfloat16* __restrict__ outH, __nv_bfloat16* __restrict__ outL)
{
    __shared__ __align__(16) __nv_bfloat16 sAhi[128 * PADK];
    __shared__ __align__(16) __nv_bfloat16 sAlo[128 * PADK];
    __shared__ __align__(16) __nv_bfloat16 sBhi[128 * PADK];
    __shared__ __align__(16) __nv_bfloat16 sBlo[128 * PADK];

    const int m0 = blockIdx.y * 128;
    const int n0 = blockIdx.x * 128;
    const int tid = threadIdx.x;
    const int lane = tid & 31;
    const int warp = tid >> 5;
    const int wm = warp & 1;          // 0..1 -> 64 rows
    const int wn = warp >> 1;         // 0..3 -> 32 cols

    float acc[4][4][4];
    #pragma unroll
    for (int i = 0; i < 4; i++)
        #pragma unroll
        for (int j = 0; j < 4; j++)
            #pragma unroll
            for (int e = 0; e < 4; e++) acc[i][j][e] = 0.f;

    const uint32_t aRowHi = smem_u32(&sAhi[(wm * 64 + (lane & 15)) * PADK + (lane >> 4) * 8]);
    const uint32_t aRowLo = smem_u32(&sAlo[(wm * 64 + (lane & 15)) * PADK + (lane >> 4) * 8]);
    const uint32_t bRowHi = smem_u32(&sBhi[(wn * 32 + (lane & 7)) * PADK + ((lane >> 3) & 1) * 8]);
    const uint32_t bRowLo = smem_u32(&sBlo[(wn * 32 + (lane & 7)) * PADK + ((lane >> 3) & 1) * 8]);

    for (int kc = 0; kc < C_ / 32; kc++) {
        const int k0 = kc * 32;
        #pragma unroll
        for (int u = 0; u < 4; u++) {
            int idx = u * 256 + tid;          // 1024 float4 per operand
            int row = idx >> 3;               // 0..127
            int c4  = idx & 7;
            uint32_t h01, h23, l01, l23;

            float4 xv = *(const float4*)(X + (size_t)(m0 + row) * C_ + k0 + c4 * 4);
            CVT_BF16X2(h01, xv.x, xv.y);
            CVT_BF16X2(h23, xv.z, xv.w);
            float r0 = xv.x - __uint_as_float(h01 << 16);
            float r1 = xv.y - __uint_as_float(h01 & 0xffff0000u);
            float r2 = xv.z - __uint_as_float(h23 << 16);
            float r3 = xv.w - __uint_as_float(h23 & 0xffff0000u);
            CVT_BF16X2(l01, r0, r1);
            CVT_BF16X2(l23, r2, r3);
            *(uint2*)&sAhi[row * PADK + c4 * 4] = make_uint2(h01, h23);
            *(uint2*)&sAlo[row * PADK + c4 * 4] = make_uint2(l01, l23);

            float4 wv = *(const float4*)(W + (size_t)(n0 + row) * C_ + k0 + c4 * 4);
            CVT_BF16X2(h01, wv.x, wv.y);
            CVT_BF16X2(h23, wv.z, wv.w);
            r0 = wv.x - __uint_as_float(h01 << 16);
            r1 = wv.y - __uint_as_float(h01 & 0xffff0000u);
            r2 = wv.z - __uint_as_float(h23 << 16);
            r3 = wv.w - __uint_as_float(h23 & 0xffff0000u);
            CVT_BF16X2(l01, r0, r1);
            CVT_BF16X2(l23, r2, r3);
            *(uint2*)&sBhi[row * PADK + c4 * 4] = make_uint2(h01, h23);
            *(uint2*)&sBlo[row * PADK + c4 * 4] = make_uint2(l01, l23);
        }
        __syncthreads();

        #pragma unroll
        for (int ks = 0; ks < 2; ks++) {
            const uint32_t koff = ks * 16 * 2;
            uint32_t ahi[4][4], alo[4][4], bhi[4][2], blo[4][2];
            #pragma unroll
            for (int mi = 0; mi < 4; mi++) {
                uint32_t ofs = mi * 16 * PADK * 2 + koff;
                LDMATRIX_X4(ahi[mi][0], ahi[mi][1], ahi[mi][2], ahi[mi][3], aRowHi + ofs);
                LDMATRIX_X4(alo[mi][0], alo[mi][1], alo[mi][2], alo[mi][3], aRowLo + ofs);
            }
            #pragma unroll
            for (int ni = 0; ni < 4; ni++) {
                uint32_t ofs = ni * 8 * PADK * 2 + koff;
                LDMATRIX_X2(bhi[ni][0], bhi[ni][1], bRowHi + ofs);
                LDMATRIX_X2(blo[ni][0], blo[ni][1], bRowLo + ofs);
            }
            #pragma unroll
            for (int mi = 0; mi < 4; mi++)
                #pragma unroll
                for (int ni = 0; ni < 4; ni++) {
                    MMA_BF16(acc[mi][ni], ahi[mi], bhi[ni]);
                    MMA_BF16(acc[mi][ni], ahi[mi], blo[ni]);
                    MMA_BF16(acc[mi][ni], alo[mi], bhi[ni]);
                }
        }
        __syncthreads();
    }

    // epilogue
    #pragma unroll
    for (int mi = 0; mi < 4; mi++)
        #pragma unroll
        for (int ni = 0; ni < 4; ni++)
            #pragma unroll
            for (int ep = 0; ep < 2; ep++) {
                int m = m0 + wm * 64 + mi * 16 + (lane >> 2) + ep * 8;
                int n = n0 + wn * 32 + ni * 8 + (lane & 3) * 2;
                float v0 = acc[mi][ni][ep * 2 + 0];
                float v1 = acc[mi][ni][ep * 2 + 1];
                if (DO_BIAS) { v0 += bias[n]; v1 += bias[n + 1]; }
                if (DO_GELU) { v0 = gelu_exact(v0); v1 = gelu_exact(v1); }
                if (DO_SCALE) { v0 *= SCALE_; v1 *= SCALE_; }
                if (HEAD_OUT) {
                    uint32_t hp, lp;
                    CVT_BF16X2(hp, v0, v1);
                    float l0 = v0 - __uint_as_float(hp << 16);
                    float l1 = v1 - __uint_as_float(hp & 0xffff0000u);
                    CVT_BF16X2(lp, l0, l1);
                    int bb = m >> 12, nr = m & (N_ - 1);
                    int h = n >> 6, d = n & 63;
                    size_t eidx = ((((size_t)(bb * H_ + h)) * N_ + nr) * D_ + d);
                    *(uint32_t*)((char*)outH + eidx * 2) = hp;
                    *(uint32_t*)((char*)outL + eidx * 2) = lp;
                } else {
                    *(float2*)(outF + (size_t)m * C_ + n) = make_float2(v0, v1);
                }
            }
}

// ------------------------------------------------- HMMA flash attention
// CTA: 128 q-rows x one (b,h). 8 warps; warp owns 16 q-rows x all 64 keys.
// Split-bf16 (3-pass) for both QK^T and PV. 2-stage cp.async pipeline on K/V.
#define AP 72              // smem row pitch in bf16 (144 B)
#define APB 144
#define SQH 0
#define SQL (128*APB)                 // 18432
#define SBUF0 (2*128*APB)             // 36864
#define STILE (64*APB)                // 9216
#define SBUFSZ (4*STILE)              // 36864
#define ATT_SMEM (SBUF0 + 2*SBUFSZ)   // 110592

__global__ __launch_bounds__(256, 2)
void attn_mma(float* __restrict__ xout)
{
    extern __shared__ __align__(16) char sm[];
    const uint32_t sb = smem_u32(sm);

    const int bh = blockIdx.y;
    const int b  = bh / H_, h = bh - b * H_;
    const int q0 = blockIdx.x * 128;
    const int tid = threadIdx.x;
    const int lane = tid & 31;
    const int w = tid >> 5;

    const char* Qh = (const char*)(g_qh + ((size_t)bh * N_ + q0) * D_);
    const char* Ql = (const char*)(g_ql + ((size_t)bh * N_ + q0) * D_);
    const char* Kh = (const char*)(g_kh + (size_t)bh * N_ * D_);
    const char* Kl = (const char*)(g_kl + (size_t)bh * N_ * D_);
    const char* Vh = (const char*)(g_vh + (size_t)bh * N_ * D_);
    const char* Vl = (const char*)(g_vl + (size_t)bh * N_ * D_);

    // Q tiles: 2 arrays x 128 rows x 8 16B-chunks = 2048 -> 8/thread
    #pragma unroll
    for (int i = 0; i < 4; i++) {
        int idx = i * 256 + tid;
        int row = idx >> 3, ch = idx & 7;
        cp16(sb + SQH + row * APB + ch * 16, Qh + row * 128 + ch * 16);
        cp16(sb + SQL + row * APB + ch * 16, Ql + row * 128 + ch * 16);
    }
    // prologue: tile 0 -> buf 0
    {
        const char* basep[4] = {Kh, Kl, Vh, Vl};
        #pragma unroll
        for (int i = 0; i < 8; i++) {
            int idx = i * 256 + tid;
            int arr = i >> 1;
            int rem = idx & 511;
            int row = rem >> 3, ch = rem & 7;
            cp16(sb + SBUF0 + arr * STILE + row * APB + ch * 16,
                 basep[arr] + (size_t)row * 128 + ch * 16);
        }
    }
    CP_COMMIT();

    float o[8][4];
    #pragma unroll
    for (int g = 0; g < 8; g++)
        #pragma unroll
        for (int e = 0; e < 4; e++) o[g][e] = 0.f;
    float mA = -1e30f, mB = -1e30f, lA = 0.f, lB = 0.f;

    const int wq = w * 16;
    const uint32_t aQh = sb + SQH + (wq + (lane & 15)) * APB + ((lane >> 4) << 4);
    const uint32_t aQl = sb + SQL + (wq + (lane & 15)) * APB + ((lane >> 4) << 4);
    const uint32_t rowsel = (lane & 15) * APB + ((lane >> 4) << 4);

    for (int t = 0; t < 64; t++) {
        const int buf = t & 1;
        if (t + 1 < 64) {
            const char* basep[4] = {Kh, Kl, Vh, Vl};
            const uint32_t dbase = sb + SBUF0 + (1 - buf) * SBUFSZ;
            const size_t gofs = (size_t)(t + 1) * 64 * 128;
            #pragma unroll
            for (int i = 0; i < 8; i++) {
                int idx = i * 256 + tid;
                int arr = i >> 1;
                int rem = idx & 511;
                int row = rem >> 3, ch = rem & 7;
                cp16(dbase + arr * STILE + row * APB + ch * 16,
                     basep[arr] + gofs + (size_t)row * 128 + ch * 16);
            }
            CP_COMMIT();
            CP_WAIT(1);
        } else {
            CP_COMMIT();
            CP_WAIT(1);
        }
        __syncthreads();

        const uint32_t sKh = sb + SBUF0 + buf * SBUFSZ;
        const uint32_t sKl = sKh + STILE;
        const uint32_t sVh = sKh + 2 * STILE;
        const uint32_t sVl = sKh + 3 * STILE;

        // ---- S = QK^T (3-pass split)
        float s[8][4];
        #pragma unroll
        for (int f = 0; f < 8; f++)
            #pragma unroll
            for (int e = 0; e < 4; e++) s[f][e] = 0.f;

        #pragma unroll
        for (int ks = 0; ks < 4; ks++) {
            uint32_t qh0, qh1, qh2, qh3, ql0, ql1, ql2, ql3;
            LDMATRIX_X4(qh0, qh1, qh2, qh3, aQh + ks * 32);
            LDMATRIX_X4(ql0, ql1, ql2, ql3, aQl + ks * 32);
            #pragma unroll
            for (int p = 0; p < 4; p++) {
                uint32_t kh0, kh1, kh2, kh3, kl0, kl1, kl2, kl3;
                LDMATRIX_X4(kh0, kh1, kh2, kh3, sKh + (16 * p) * APB + rowsel + ks * 32);
                LDMATRIX_X4(kl0, kl1, kl2, kl3, sKl + (16 * p) * APB + rowsel + ks * 32);
                mma16816(s[2*p],   qh0, qh1, qh2, qh3, kh0, kh2);
                mma16816(s[2*p+1], qh0, qh1, qh2, qh3, kh1, kh3);
                mma16816(s[2*p],   qh0, qh1, qh2, qh3, kl0, kl2);
                mma16816(s[2*p+1], qh0, qh1, qh2, qh3, kl1, kl3);
                mma16816(s[2*p],   ql0, ql1, ql2, ql3, kh0, kh2);
                mma16816(s[2*p+1], ql0, ql1, ql2, ql3, kh1, kh3);
            }
        }

        // ---- online softmax (warp-local; rows: A=lane>>2, B=A+8)
        float mxA = -1e30f, mxB = -1e30f;
        #pragma unroll
        for (int f = 0; f < 8; f++) {
            mxA = fmaxf(mxA, fmaxf(s[f][0], s[f][1]));
            mxB = fmaxf(mxB, fmaxf(s[f][2], s[f][3]));
        }
        mxA = fmaxf(mxA, __shfl_xor_sync(0xffffffffu, mxA, 1, 4));
        mxA = fmaxf(mxA, __shfl_xor_sync(0xffffffffu, mxA, 2, 4));
        mxB = fmaxf(mxB, __shfl_xor_sync(0xffffffffu, mxB, 1, 4));
        mxB = fmaxf(mxB, __shfl_xor_sync(0xffffffffu, mxB, 2, 4));
        float mnA = fmaxf(mA, mxA), mnB = fmaxf(mB, mxB);
        float alA = __expf(mA - mnA), alB = __expf(mB - mnB);
        mA = mnA; mB = mnB;
        float suA = 0.f, suB = 0.f;
        #pragma unroll
        for (int f = 0; f < 8; f++) {
            s[f][0] = __expf(s[f][0] - mnA); suA += s[f][0];
            s[f][1] = __expf(s[f][1] - mnA); suA += s[f][1];
            s[f][2] = __expf(s[f][2] - mnB); suB += s[f][2];
            s[f][3] = __expf(s[f][3] - mnB); suB += s[f][3];
        }
        suA += __shfl_xor_sync(0xffffffffu, suA, 1, 4);
        suA += __shfl_xor_sync(0xffffffffu, suA, 2, 4);
        suB += __shfl_xor_sync(0xffffffffu, suB, 1, 4);
        suB += __shfl_xor_sync(0xffffffffu, suB, 2, 4);
        lA = lA * alA + suA;
        lB = lB * alB + suB;
        #pragma unroll
        for (int g = 0; g < 8; g++) {
            o[g][0] *= alA; o[g][1] *= alA;
            o[g][2] *= alB; o[g][3] *= alB;
        }

        // ---- O += P @ V (P a-frags packed from S c-frags; 3-pass split)
        #pragma unroll
        for (int kt = 0; kt < 4; kt++) {
            uint32_t ph0, ph1, ph2, ph3, pl0, pl1, pl2, pl3;
            CVT_BF16X2(ph0, s[2*kt][0],   s[2*kt][1]);
            CVT_BF16X2(ph1, s[2*kt][2],   s[2*kt][3]);
            CVT_BF16X2(ph2, s[2*kt+1][0], s[2*kt+1][1]);
            CVT_BF16X2(ph3, s[2*kt+1][2], s[2*kt+1][3]);
            {
                float a0 = s[2*kt][0]   - __uint_as_float(ph0 << 16);
                float a1 = s[2*kt][1]   - __uint_as_float(ph0 & 0xffff0000u);
                float a2 = s[2*kt][2]   - __uint_as_float(ph1 << 16);
                float a3 = s[2*kt][3]   - __uint_as_float(ph1 & 0xffff0000u);
                CVT_BF16X2(pl0, a0, a1);
                CVT_BF16X2(pl1, a2, a3);
                a0 = s[2*kt+1][0] - __uint_as_float(ph2 << 16);
                a1 = s[2*kt+1][1] - __uint_as_float(ph2 & 0xffff0000u);
                a2 = s[2*kt+1][2] - __uint_as_float(ph3 << 16);
                a3 = s[2*kt+1][3] - __uint_as_float(ph3 & 0xffff0000u);
                CVT_BF16X2(pl2, a0, a1);
                CVT_BF16X2(pl3, a2, a3);
            }
            #pragma unroll
            for (int g = 0; g < 4; g++) {
                uint32_t vh0, vh1, vh2, vh3, vl0, vl1, vl2, vl3;
                LDMATRIX_X4_T(vh0, vh1, vh2, vh3, sVh + (16 * kt) * APB + rowsel + g * 32);
                LDMATRIX_X4_T(vl0, vl1, vl2, vl3, sVl + (16 * kt) * APB + rowsel + g * 32);
                mma16816(o[2*g],   ph0, ph1, ph2, ph3, vh0, vh1);
                mma16816(o[2*g+1], ph0, ph1, ph2, ph3, vh2, vh3);
                mma16816(o[2*g],   ph0, ph1, ph2, ph3, vl0, vl1);
                mma16816(o[2*g+1], ph0, ph1, ph2, ph3, vl2, vl3);
                mma16816(o[2*g],   pl0, pl1, pl2, pl3, vh0, vh1);
                mma16816(o[2*g+1], pl0, pl1, pl2, pl3, vh2, vh3);
            }
        }
        __syncthreads();   // buffer consumed; safe to refill next iter
    }

    // ---- normalize + write [B,N,C]
    const float ivA = 1.f / lA, ivB = 1.f / lB;
    const int rowA = q0 + wq + (lane >> 2);
    const int col0 = h * D_ + 2 * (lane & 3);
    #pragma unroll
    for (int g = 0; g < 8; g++) {
        *(float2*)(xout + (size_t)(b * N_ + rowA) * C_ + col0 + 8 * g)
            = make_float2(o[g][0] * ivA, o[g][1] * ivA);
        *(float2*)(xout + (size_t)(b * N_ + rowA + 8) * C_ + col0 + 8 * g)
            = make_float2(o[g][2] * ivB, o[g][3] * ivB);
    }
}

extern "C" void kernel_launch(void* const* d_in, const int* in_sizes, int n_in,
                              void* d_out, int out_size)
{
    const float* query = (const float*)d_in[0];
    const float* key   = (const float*)d_in[1];
    const float* value = (const float*)d_in[2];
    const float* Wq    = (const float*)d_in[3];
    const float* Wk    = (const float*)d_in[4];
    const float* bk    = (const float*)d_in[5];
    const float* Wv    = (const float*)d_in[6];
    const float* Wp    = (const float*)d_in[7];
    const float* bp    = (const float*)d_in[8];
    float* out = (float*)d_out;

    __nv_bfloat16 *pqh, *pql, *pkh, *pkl, *pvh, *pvl;
    float* px;
    cudaGetSymbolAddress((void**)&pqh, g_qh);
    cudaGetSymbolAddress((void**)&pql, g_ql);
    cudaGetSymbolAddress((void**)&pkh, g_kh);
    cudaGetSymbolAddress((void**)&pkl, g_kl);
    cudaGetSymbolAddress((void**)&pvh, g_vh);
    cudaGetSymbolAddress((void**)&pvl, g_vl);
    cudaGetSymbolAddress((void**)&px,  g_x);

    static bool attr_done = false;
    if (!attr_done) {
        cudaFuncSetAttribute(attn_mma, cudaFuncAttributeMaxDynamicSharedMemorySize, ATT_SMEM);
        attr_done = true;
    }

    dim3 gp(6, 64);
    // Q: scale folded; K: bias+gelu; V: plain -> split bf16 head-major
    proj_mma<0,0,1,1><<<gp, 256>>>(query, Wq, nullptr, nullptr, pqh, pql);
    proj_mma<1,1,0,1><<<gp, 256>>>(key,   Wk, bk,      nullptr, pkh, pkl);
    proj_mma<0,0,0,1><<<gp, 256>>>(value, Wv, nullptr, nullptr, pvh, pvl);

    attn_mma<<<dim3(32, 24), 256, ATT_SMEM>>>(px);

    proj_mma<1,0,0,0><<<gp, 256>>>(px, Wp, bp, out, nullptr, nullptr);
}

// round 6
// speedup vs baseline: 3.3921x; 1.4405x over previous
#include <cuda_runtime.h>
#include <cuda_bf16.h>
#include <cuda_fp16.h>
#include <math.h>
#include <stdint.h>

#define B_ 2
#define N_ 4096
#define C_ 768
#define H_ 12
#define D_ 64
#define M_ (B_*N_)
#define SCALE_ 0.125f

// ---- scratch (allocation-free) ----
// split-bf16 copies of inputs and weights
__device__ __align__(16) __nv_bfloat16 g_iqh[(size_t)M_*C_], g_iql[(size_t)M_*C_];
__device__ __align__(16) __nv_bfloat16 g_ikh[(size_t)M_*C_], g_ikl[(size_t)M_*C_];
__device__ __align__(16) __nv_bfloat16 g_ivh[(size_t)M_*C_], g_ivl[(size_t)M_*C_];
__device__ __align__(16) __nv_bfloat16 g_wqh[(size_t)C_*C_], g_wql[(size_t)C_*C_];
__device__ __align__(16) __nv_bfloat16 g_wkh[(size_t)C_*C_], g_wkl[(size_t)C_*C_];
__device__ __align__(16) __nv_bfloat16 g_wvh[(size_t)C_*C_], g_wvl[(size_t)C_*C_];
__device__ __align__(16) __nv_bfloat16 g_wph[(size_t)C_*C_], g_wpl[(size_t)C_*C_];
// projected Q/K (split bf16, head-major [B,H,N,D]); V fp16
__device__ __align__(16) __nv_bfloat16 g_qh[(size_t)B_*H_*N_*D_], g_ql[(size_t)B_*H_*N_*D_];
__device__ __align__(16) __nv_bfloat16 g_kh[(size_t)B_*H_*N_*D_], g_kl[(size_t)B_*H_*N_*D_];
__device__ __align__(16) __half       g_v16[(size_t)B_*H_*N_*D_];
// attention output (split bf16, [B,N,C])
__device__ __align__(16) __nv_bfloat16 g_xh[(size_t)M_*C_], g_xl[(size_t)M_*C_];

__device__ __forceinline__ float gelu_exact(float x) {
    return 0.5f * x * (1.0f + erff(x * 0.70710678118654752f));
}
__device__ __forceinline__ uint32_t smem_u32(const void* p) {
    uint32_t a;
    asm("{ .reg .u64 t; cvta.to.shared.u64 t, %1; cvt.u32.u64 %0, t; }" : "=r"(a) : "l"(p));
    return a;
}
// res = {hi: bf16(b), lo: bf16(a)}
#define CVT_BF16X2(res, a, b) \
    asm("cvt.rn.bf16x2.f32 %0, %1, %2;" : "=r"(res) : "f"(b), "f"(a))
#define CVT_F16X2(res, a, b) \
    asm("cvt.rn.f16x2.f32 %0, %1, %2;" : "=r"(res) : "f"(b), "f"(a))

#define LDMATRIX_X4(r0, r1, r2, r3, addr) \
    asm volatile("ldmatrix.sync.aligned.m8n8.x4.shared.b16 {%0,%1,%2,%3}, [%4];" \
        : "=r"(r0), "=r"(r1), "=r"(r2), "=r"(r3) : "r"(addr))
#define LDMATRIX_X4_T(r0, r1, r2, r3, addr) \
    asm volatile("ldmatrix.sync.aligned.m8n8.x4.trans.shared.b16 {%0,%1,%2,%3}, [%4];" \
        : "=r"(r0), "=r"(r1), "=r"(r2), "=r"(r3) : "r"(addr))
#define LDMATRIX_X2(r0, r1, addr) \
    asm volatile("ldmatrix.sync.aligned.m8n8.x2.shared.b16 {%0,%1}, [%2];" \
        : "=r"(r0), "=r"(r1) : "r"(addr))

__device__ __forceinline__ void mma16816(float* d, uint32_t a0, uint32_t a1,
                                         uint32_t a2, uint32_t a3,
                                         uint32_t b0, uint32_t b1) {
    asm volatile("mma.sync.aligned.m16n8k16.row.col.f32.bf16.bf16.f32 "
        "{%0,%1,%2,%3}, {%4,%5,%6,%7}, {%8,%9}, {%0,%1,%2,%3};"
        : "+f"(d[0]), "+f"(d[1]), "+f"(d[2]), "+f"(d[3])
        : "r"(a0), "r"(a1), "r"(a2), "r"(a3), "r"(b0), "r"(b1));
}
__device__ __forceinline__ void mma16816h(float* d, uint32_t a0, uint32_t a1,
                                          uint32_t a2, uint32_t a3,
                                          uint32_t b0, uint32_t b1) {
    asm volatile("mma.sync.aligned.m16n8k16.row.col.f32.f16.f16.f32 "
        "{%0,%1,%2,%3}, {%4,%5,%6,%7}, {%8,%9}, {%0,%1,%2,%3};"
        : "+f"(d[0]), "+f"(d[1]), "+f"(d[2]), "+f"(d[3])
        : "r"(a0), "r"(a1), "r"(a2), "r"(a3), "r"(b0), "r"(b1));
}
#define MMA_BF16(d, a, b) \
    asm volatile("mma.sync.aligned.m16n8k16.row.col.f32.bf16.bf16.f32 " \
        "{%0,%1,%2,%3}, {%4,%5,%6,%7}, {%8,%9}, {%0,%1,%2,%3};" \
        : "+f"((d)[0]), "+f"((d)[1]), "+f"((d)[2]), "+f"((d)[3]) \
        : "r"((a)[0]), "r"((a)[1]), "r"((a)[2]), "r"((a)[3]), "r"((b)[0]), "r"((b)[1]))

__device__ __forceinline__ void cp16(uint32_t saddr, const void* g) {
    asm volatile("cp.async.ca.shared.global [%0], [%1], 16;" :: "r"(saddr), "l"(g));
}
#define CP_COMMIT() asm volatile("cp.async.commit_group;" ::: "memory")
#define CP_WAIT(n)  asm volatile("cp.async.wait_group %0;" :: "n"(n) : "memory")

// ------------------------------------------------ fp32 -> split bf16 converter
__global__ void split_f32(const float4* __restrict__ in, uint2* __restrict__ hi,
                          uint2* __restrict__ lo, int n4)
{
    int i = blockIdx.x * blockDim.x + threadIdx.x;
    if (i >= n4) return;
    float4 v = in[i];
    uint32_t h01, h23, l01, l23;
    CVT_BF16X2(h01, v.x, v.y);
    CVT_BF16X2(h23, v.z, v.w);
    float r0 = v.x - __uint_as_float(h01 << 16);
    float r1 = v.y - __uint_as_float(h01 & 0xffff0000u);
    float r2 = v.z - __uint_as_float(h23 << 16);
    float r3 = v.w - __uint_as_float(h23 & 0xffff0000u);
    CVT_BF16X2(l01, r0, r1);
    CVT_BF16X2(l23, r2, r3);
    hi[i] = make_uint2(h01, h23);
    lo[i] = make_uint2(l01, l23);
}

// ------------------------------------------------------------ HMMA projection
// Operands pre-split bf16. Tile 128x128, BK=32, double-buffered cp.async.
// OUT_MODE: 0 = fp32 [M][C], 1 = split bf16 head-major, 2 = fp16 head-major
#define PROW 80                  // smem row pitch in bytes (40 bf16)
#define PTILE 10240              // 128 * 80
#define PSTAGE 40960             // 4 tiles
#define PROJ_SMEM 81920

template<int DO_BIAS, int DO_GELU, int DO_SCALE, int OUT_MODE>
__global__ __launch_bounds__(256, 2)
void proj2(const __nv_bfloat16* __restrict__ Xh, const __nv_bfloat16* __restrict__ Xl,
           const __nv_bfloat16* __restrict__ Wh, const __nv_bfloat16* __restrict__ Wl,
           const float* __restrict__ bias, float* __restrict__ outF,
           __nv_bfloat16* __restrict__ outH, __nv_bfloat16* __restrict__ outL,
           __half* __restrict__ outV)
{
    extern __shared__ __align__(16) char sm[];
    const uint32_t sb = smem_u32(sm);

    const int m0 = blockIdx.y * 128;
    const int n0 = blockIdx.x * 128;
    const int tid = threadIdx.x;
    const int lane = tid & 31;
    const int warp = tid >> 5;
    const int wm = warp & 1;
    const int wn = warp >> 1;

    const char* src[4] = {
        (const char*)(Xh + (size_t)m0 * C_), (const char*)(Xl + (size_t)m0 * C_),
        (const char*)(Wh + (size_t)n0 * C_), (const char*)(Wl + (size_t)n0 * C_) };

    float acc[4][4][4];
    #pragma unroll
    for (int i = 0; i < 4; i++)
        #pragma unroll
        for (int j = 0; j < 4; j++)
            #pragma unroll
            for (int e = 0; e < 4; e++) acc[i][j][e] = 0.f;

    // prologue: chunk 0 -> stage 0
    #pragma unroll
    for (int u = 0; u < 8; u++) {
        int idx = u * 256 + tid;
        int arr = idx >> 9, rem = idx & 511;
        int row = rem >> 2, ch = rem & 3;
        cp16(sb + arr * PTILE + row * PROW + ch * 16,
             src[arr] + (size_t)row * (C_ * 2) + ch * 16);
    }
    CP_COMMIT();

    for (int kc = 0; kc < C_ / 32; kc++) {
        const int st = kc & 1;
        CP_WAIT(0);
        __syncthreads();
        if (kc + 1 < C_ / 32) {
            const uint32_t dbase = sb + (st ^ 1) * PSTAGE;
            const int k0b = (kc + 1) * 64;       // bytes into a row
            #pragma unroll
            for (int u = 0; u < 8; u++) {
                int idx = u * 256 + tid;
                int arr = idx >> 9, rem = idx & 511;
                int row = rem >> 2, ch = rem & 3;
                cp16(dbase + arr * PTILE + row * PROW + ch * 16,
                     src[arr] + (size_t)row * (C_ * 2) + k0b + ch * 16);
            }
            CP_COMMIT();
        }

        const uint32_t abase = sb + st * PSTAGE;
        const uint32_t aHi = abase + (wm * 64 + (lane & 15)) * PROW + ((lane >> 4) << 4);
        const uint32_t aLo = aHi + PTILE;
        const uint32_t bHi = abase + 2 * PTILE + (wn * 32 + (lane & 7)) * PROW + (((lane >> 3) & 1) << 4);
        const uint32_t bLo = bHi + PTILE;

        #pragma unroll
        for (int ks = 0; ks < 2; ks++) {
            const uint32_t koff = ks * 32;
            uint32_t ahi[4][4], alo[4][4], bhi[4][2], blo[4][2];
            #pragma unroll
            for (int mi = 0; mi < 4; mi++) {
                uint32_t ofs = mi * 16 * PROW + koff;
                LDMATRIX_X4(ahi[mi][0], ahi[mi][1], ahi[mi][2], ahi[mi][3], aHi + ofs);
                LDMATRIX_X4(alo[mi][0], alo[mi][1], alo[mi][2], alo[mi][3], aLo + ofs);
            }
            #pragma unroll
            for (int ni = 0; ni < 4; ni++) {
                uint32_t ofs = ni * 8 * PROW + koff;
                LDMATRIX_X2(bhi[ni][0], bhi[ni][1], bHi + ofs);
                LDMATRIX_X2(blo[ni][0], blo[ni][1], bLo + ofs);
            }
            #pragma unroll
            for (int mi = 0; mi < 4; mi++)
                #pragma unroll
                for (int ni = 0; ni < 4; ni++) {
                    MMA_BF16(acc[mi][ni], ahi[mi], bhi[ni]);
                    MMA_BF16(acc[mi][ni], ahi[mi], blo[ni]);
                    MMA_BF16(acc[mi][ni], alo[mi], bhi[ni]);
                }
        }
    }

    // epilogue
    #pragma unroll
    for (int mi = 0; mi < 4; mi++)
        #pragma unroll
        for (int ni = 0; ni < 4; ni++)
            #pragma unroll
            for (int ep = 0; ep < 2; ep++) {
                int m = m0 + wm * 64 + mi * 16 + (lane >> 2) + ep * 8;
                int n = n0 + wn * 32 + ni * 8 + (lane & 3) * 2;
                float v0 = acc[mi][ni][ep * 2 + 0];
                float v1 = acc[mi][ni][ep * 2 + 1];
                if (DO_BIAS) { v0 += bias[n]; v1 += bias[n + 1]; }
                if (DO_GELU) { v0 = gelu_exact(v0); v1 = gelu_exact(v1); }
                if (DO_SCALE) { v0 *= SCALE_; v1 *= SCALE_; }
                if (OUT_MODE == 1 || OUT_MODE == 2) {
                    int bb = m >> 12, nr = m & (N_ - 1);
                    int h = n >> 6, d = n & 63;
                    size_t eidx = ((((size_t)(bb * H_ + h)) * N_ + nr) * D_ + d);
                    if (OUT_MODE == 1) {
                        uint32_t hp, lp;
                        CVT_BF16X2(hp, v0, v1);
                        float l0 = v0 - __uint_as_float(hp << 16);
                        float l1 = v1 - __uint_as_float(hp & 0xffff0000u);
                        CVT_BF16X2(lp, l0, l1);
                        *(uint32_t*)((char*)outH + eidx * 2) = hp;
                        *(uint32_t*)((char*)outL + eidx * 2) = lp;
                    } else {
                        uint32_t vp;
                        CVT_F16X2(vp, v0, v1);
                        *(uint32_t*)((char*)outV + eidx * 2) = vp;
                    }
                } else {
                    *(float2*)(outF + (size_t)m * C_ + n) = make_float2(v0, v1);
                }
            }
}

// ------------------------------------------------- HMMA flash attention
// QK^T: split-bf16 3-pass.  P·V: single-pass fp16.
#define APB 144
#define SQH 0
#define SQL (128*APB)                 // 18432
#define SBUF0 (2*128*APB)             // 36864
#define STILE (64*APB)                // 9216
#define SBUFSZ (3*STILE)              // 27648 (Kh, Kl, V16)
#define ATT_SMEM (SBUF0 + 2*SBUFSZ)   // 92160

__global__ __launch_bounds__(256, 2)
void attn_mma(__nv_bfloat16* __restrict__ pxh, __nv_bfloat16* __restrict__ pxl)
{
    extern __shared__ __align__(16) char sm[];
    const uint32_t sb = smem_u32(sm);

    const int bh = blockIdx.y;
    const int b  = bh / H_, h = bh - b * H_;
    const int q0 = blockIdx.x * 128;
    const int tid = threadIdx.x;
    const int lane = tid & 31;
    const int w = tid >> 5;

    const char* Qh = (const char*)(g_qh + ((size_t)bh * N_ + q0) * D_);
    const char* Ql = (const char*)(g_ql + ((size_t)bh * N_ + q0) * D_);
    const char* src[3] = {
        (const char*)(g_kh + (size_t)bh * N_ * D_),
        (const char*)(g_kl + (size_t)bh * N_ * D_),
        (const char*)(g_v16 + (size_t)bh * N_ * D_) };

    // prologue: Q tiles + K/V tile 0
    #pragma unroll
    for (int i = 0; i < 4; i++) {
        int idx = i * 256 + tid;
        int row = idx >> 3, ch = idx & 7;
        cp16(sb + SQH + row * APB + ch * 16, Qh + row * 128 + ch * 16);
        cp16(sb + SQL + row * APB + ch * 16, Ql + row * 128 + ch * 16);
    }
    #pragma unroll
    for (int i = 0; i < 6; i++) {
        int idx = i * 256 + tid;
        int arr = idx >> 9, rem = idx & 511;
        int row = rem >> 3, ch = rem & 7;
        cp16(sb + SBUF0 + arr * STILE + row * APB + ch * 16,
             src[arr] + (size_t)row * 128 + ch * 16);
    }
    CP_COMMIT();

    float o[8][4];
    #pragma unroll
    for (int g = 0; g < 8; g++)
        #pragma unroll
        for (int e = 0; e < 4; e++) o[g][e] = 0.f;
    float mA = -1e30f, mB = -1e30f, lA = 0.f, lB = 0.f;

    const int wq = w * 16;
    const uint32_t aQh = sb + SQH + (wq + (lane & 15)) * APB + ((lane >> 4) << 4);
    const uint32_t aQl = sb + SQL + (wq + (lane & 15)) * APB + ((lane >> 4) << 4);
    const uint32_t rowsel = (lane & 15) * APB + ((lane >> 4) << 4);

    for (int t = 0; t < 64; t++) {
        const int buf = t & 1;
        CP_WAIT(0);
        __syncthreads();
        if (t + 1 < 64) {
            const uint32_t dbase = sb + SBUF0 + (1 - buf) * SBUFSZ;
            const size_t gofs = (size_t)(t + 1) * 64 * 128;
            #pragma unroll
            for (int i = 0; i < 6; i++) {
                int idx = i * 256 + tid;
                int arr = idx >> 9, rem = idx & 511;
                int row = rem >> 3, ch = rem & 7;
                cp16(dbase + arr * STILE + row * APB + ch * 16,
                     src[arr] + gofs + (size_t)row * 128 + ch * 16);
            }
            CP_COMMIT();
        }

        const uint32_t sKh = sb + SBUF0 + buf * SBUFSZ;
        const uint32_t sKl = sKh + STILE;
        const uint32_t sV  = sKh + 2 * STILE;

        // ---- S = QK^T (3-pass split bf16)
        float s[8][4];
        #pragma unroll
        for (int f = 0; f < 8; f++)
            #pragma unroll
            for (int e = 0; e < 4; e++) s[f][e] = 0.f;

        #pragma unroll
        for (int ks = 0; ks < 4; ks++) {
            uint32_t qh0, qh1, qh2, qh3, ql0, ql1, ql2, ql3;
            LDMATRIX_X4(qh0, qh1, qh2, qh3, aQh + ks * 32);
            LDMATRIX_X4(ql0, ql1, ql2, ql3, aQl + ks * 32);
            #pragma unroll
            for (int p = 0; p < 4; p++) {
                uint32_t kh0, kh1, kh2, kh3, kl0, kl1, kl2, kl3;
                LDMATRIX_X4(kh0, kh1, kh2, kh3, sKh + (16 * p) * APB + rowsel + ks * 32);
                LDMATRIX_X4(kl0, kl1, kl2, kl3, sKl + (16 * p) * APB + rowsel + ks * 32);
                mma16816(s[2*p],   qh0, qh1, qh2, qh3, kh0, kh2);
                mma16816(s[2*p+1], qh0, qh1, qh2, qh3, kh1, kh3);
                mma16816(s[2*p],   qh0, qh1, qh2, qh3, kl0, kl2);
                mma16816(s[2*p+1], qh0, qh1, qh2, qh3, kl1, kl3);
                mma16816(s[2*p],   ql0, ql1, ql2, ql3, kh0, kh2);
                mma16816(s[2*p+1], ql0, ql1, ql2, ql3, kh1, kh3);
            }
        }

        // ---- online softmax (rows: A = lane>>2, B = A+8)
        float mxA = -1e30f, mxB = -1e30f;
        #pragma unroll
        for (int f = 0; f < 8; f++) {
            mxA = fmaxf(mxA, fmaxf(s[f][0], s[f][1]));
            mxB = fmaxf(mxB, fmaxf(s[f][2], s[f][3]));
        }
        mxA = fmaxf(mxA, __shfl_xor_sync(0xffffffffu, mxA, 1, 4));
        mxA = fmaxf(mxA, __shfl_xor_sync(0xffffffffu, mxA, 2, 4));
        mxB = fmaxf(mxB, __shfl_xor_sync(0xffffffffu, mxB, 1, 4));
        mxB = fmaxf(mxB, __shfl_xor_sync(0xffffffffu, mxB, 2, 4));
        float mnA = fmaxf(mA, mxA), mnB = fmaxf(mB, mxB);
        float alA = __expf(mA - mnA), alB = __expf(mB - mnB);
        mA = mnA; mB = mnB;
        float suA = 0.f, suB = 0.f;
        #pragma unroll
        for (int f = 0; f < 8; f++) {
            s[f][0] = __expf(s[f][0] - mnA); suA += s[f][0];
            s[f][1] = __expf(s[f][1] - mnA); suA += s[f][1];
            s[f][2] = __expf(s[f][2] - mnB); suB += s[f][2];
            s[f][3] = __expf(s[f][3] - mnB); suB += s[f][3];
        }
        suA += __shfl_xor_sync(0xffffffffu, suA, 1, 4);
        suA += __shfl_xor_sync(0xffffffffu, suA, 2, 4);
        suB += __shfl_xor_sync(0xffffffffu, suB, 1, 4);
        suB += __shfl_xor_sync(0xffffffffu, suB, 2, 4);
        lA = lA * alA + suA;
        lB = lB * alB + suB;
        #pragma unroll
        for (int g = 0; g < 8; g++) {
            o[g][0] *= alA; o[g][1] *= alA;
            o[g][2] *= alB; o[g][3] *= alB;
        }

        // ---- O += P @ V  (single-pass fp16)
        #pragma unroll
        for (int kt = 0; kt < 4; kt++) {
            uint32_t ph0, ph1, ph2, ph3;
            CVT_F16X2(ph0, s[2*kt][0],   s[2*kt][1]);
            CVT_F16X2(ph1, s[2*kt][2],   s[2*kt][3]);
            CVT_F16X2(ph2, s[2*kt+1][0], s[2*kt+1][1]);
            CVT_F16X2(ph3, s[2*kt+1][2], s[2*kt+1][3]);
            #pragma unroll
            for (int g = 0; g < 4; g++) {
                uint32_t vh0, vh1, vh2, vh3;
                LDMATRIX_X4_T(vh0, vh1, vh2, vh3, sV + (16 * kt) * APB + rowsel + g * 32);
                mma16816h(o[2*g],   ph0, ph1, ph2, ph3, vh0, vh1);
                mma16816h(o[2*g+1], ph0, ph1, ph2, ph3, vh2, vh3);
            }
        }
    }

    // ---- normalize + write split bf16 [B,N,C]
    const float ivA = 1.f / lA, ivB = 1.f / lB;
    const int rowA = q0 + wq + (lane >> 2);
    const int col0 = h * D_ + 2 * (lane & 3);
    #pragma unroll
    for (int g = 0; g < 8; g++) {
        float v0 = o[g][0] * ivA, v1 = o[g][1] * ivA;
        uint32_t hp, lp;
        CVT_BF16X2(hp, v0, v1);
        float l0 = v0 - __uint_as_float(hp << 16);
        float l1 = v1 - __uint_as_float(hp & 0xffff0000u);
        CVT_BF16X2(lp, l0, l1);
        size_t e = (size_t)(b * N_ + rowA) * C_ + col0 + 8 * g;
        *(uint32_t*)((char*)pxh + e * 2) = hp;
        *(uint32_t*)((char*)pxl + e * 2) = lp;

        v0 = o[g][2] * ivB; v1 = o[g][3] * ivB;
        CVT_BF16X2(hp, v0, v1);
        l0 = v0 - __uint_as_float(hp << 16);
        l1 = v1 - __uint_as_float(hp & 0xffff0000u);
        CVT_BF16X2(lp, l0, l1);
        e = (size_t)(b * N_ + rowA + 8) * C_ + col0 + 8 * g;
        *(uint32_t*)((char*)pxh + e * 2) = hp;
        *(uint32_t*)((char*)pxl + e * 2) = lp;
    }
}

extern "C" void kernel_launch(void* const* d_in, const int* in_sizes, int n_in,
                              void* d_out, int out_size)
{
    const float* query = (const float*)d_in[0];
    const float* key   = (const float*)d_in[1];
    const float* value = (const float*)d_in[2];
    const float* Wq    = (const float*)d_in[3];
    const float* Wk    = (const float*)d_in[4];
    const float* bk    = (const float*)d_in[5];
    const float* Wv    = (const float*)d_in[6];
    const float* Wp    = (const float*)d_in[7];
    const float* bp    = (const float*)d_in[8];
    float* out = (float*)d_out;

    #define GA(sym) ({ void* _p; cudaGetSymbolAddress(&_p, sym); _p; })
    __nv_bfloat16 *iqh = (__nv_bfloat16*)GA(g_iqh), *iql = (__nv_bfloat16*)GA(g_iql);
    __nv_bfloat16 *ikh = (__nv_bfloat16*)GA(g_ikh), *ikl = (__nv_bfloat16*)GA(g_ikl);
    __nv_bfloat16 *ivh = (__nv_bfloat16*)GA(g_ivh), *ivl = (__nv_bfloat16*)GA(g_ivl);
    __nv_bfloat16 *wqh = (__nv_bfloat16*)GA(g_wqh), *wql = (__nv_bfloat16*)GA(g_wql);
    __nv_bfloat16 *wkh = (__nv_bfloat16*)GA(g_wkh), *wkl = (__nv_bfloat16*)GA(g_wkl);
    __nv_bfloat16 *wvh = (__nv_bfloat16*)GA(g_wvh), *wvl = (__nv_bfloat16*)GA(g_wvl);
    __nv_bfloat16 *wph = (__nv_bfloat16*)GA(g_wph), *wpl = (__nv_bfloat16*)GA(g_wpl);
    __nv_bfloat16 *pqh = (__nv_bfloat16*)GA(g_qh),  *pql = (__nv_bfloat16*)GA(g_ql);
    __nv_bfloat16 *pkh = (__nv_bfloat16*)GA(g_kh),  *pkl = (__nv_bfloat16*)GA(g_kl);
    __half        *pv  = (__half*)GA(g_v16);
    __nv_bfloat16 *pxh = (__nv_bfloat16*)GA(g_xh),  *pxl = (__nv_bfloat16*)GA(g_xl);

    static bool attr_done = false;
    if (!attr_done) {
        cudaFuncSetAttribute(proj2<0,0,1,1>, cudaFuncAttributeMaxDynamicSharedMemorySize, PROJ_SMEM);
        cudaFuncSetAttribute(proj2<1,1,0,1>, cudaFuncAttributeMaxDynamicSharedMemorySize, PROJ_SMEM);
        cudaFuncSetAttribute(proj2<0,0,0,2>, cudaFuncAttributeMaxDynamicSharedMemorySize, PROJ_SMEM);
        cudaFuncSetAttribute(proj2<1,0,0,0>, cudaFuncAttributeMaxDynamicSharedMemorySize, PROJ_SMEM);
        cudaFuncSetAttribute(attn_mma, cudaFuncAttributeMaxDynamicSharedMemorySize, ATT_SMEM);
        attr_done = true;
    }

    const int nx4 = M_ * C_ / 4;       // 1,572,864
    const int nw4 = C_ * C_ / 4;       // 147,456
    split_f32<<<(nx4 + 255) / 256, 256>>>((const float4*)query, (uint2*)iqh, (uint2*)iql, nx4);
    split_f32<<<(nx4 + 255) / 256, 256>>>((const float4*)key,   (uint2*)ikh, (uint2*)ikl, nx4);
    split_f32<<<(nx4 + 255) / 256, 256>>>((const float4*)value, (uint2*)ivh, (uint2*)ivl, nx4);
    split_f32<<<(nw4 + 255) / 256, 256>>>((const float4*)Wq, (uint2*)wqh, (uint2*)wql, nw4);
    split_f32<<<(nw4 + 255) / 256, 256>>>((const float4*)Wk, (uint2*)wkh, (uint2*)wkl, nw4);
    split_f32<<<(nw4 + 255) / 256, 256>>>((const float4*)Wv, (uint2*)wvh, (uint2*)wvl, nw4);
    split_f32<<<(nw4 + 255) / 256, 256>>>((const float4*)Wp, (uint2*)wph, (uint2*)wpl, nw4);

    dim3 gp(6, 64);
    proj2<0,0,1,1><<<gp, 256, PROJ_SMEM>>>(iqh, iql, wqh, wql, nullptr, nullptr, pqh, pql, nullptr);
    proj2<1,1,0,1><<<gp, 256, PROJ_SMEM>>>(ikh, ikl, wkh, wkl, bk,      nullptr, pkh, pkl, nullptr);
    proj2<0,0,0,2><<<gp, 256, PROJ_SMEM>>>(ivh, ivl, wvh, wvl, nullptr, nullptr, nullptr, nullptr, pv);

    attn_mma<<<dim3(32, 24), 256, ATT_SMEM>>>(pxh, pxl);

    proj2<1,0,0,0><<<gp, 256, PROJ_SMEM>>>(pxh, pxl, wph, wpl, bp, out, nullptr, nullptr, nullptr);
}

// round 7
// speedup vs baseline: 3.8636x; 1.1390x over previous
#include <cuda_runtime.h>
#include <cuda_bf16.h>
#include <cuda_fp16.h>
#include <math.h>
#include <stdint.h>

#define B_ 2
#define N_ 4096
#define C_ 768
#define H_ 12
#define D_ 64
#define M_ (B_*N_)
#define SCALE_ 0.125f

// ---- scratch (allocation-free), all fp16 ----
__device__ __align__(16) __half g_iqh[(size_t)M_*C_], g_iql[(size_t)M_*C_];
__device__ __align__(16) __half g_ikh[(size_t)M_*C_], g_ikl[(size_t)M_*C_];
__device__ __align__(16) __half g_ivh[(size_t)M_*C_], g_ivl[(size_t)M_*C_];
__device__ __align__(16) __half g_wqh[(size_t)C_*C_], g_wql[(size_t)C_*C_];
__device__ __align__(16) __half g_wkh[(size_t)C_*C_], g_wkl[(size_t)C_*C_];
__device__ __align__(16) __half g_wvh[(size_t)C_*C_], g_wvl[(size_t)C_*C_];
__device__ __align__(16) __half g_wph[(size_t)C_*C_], g_wpl[(size_t)C_*C_];
// projections, head-major [B,H,N,D]: Q single fp16 (pre-scaled), K split fp16, V fp16
__device__ __align__(16) __half g_q16[(size_t)B_*H_*N_*D_];
__device__ __align__(16) __half g_kh[(size_t)B_*H_*N_*D_], g_kl[(size_t)B_*H_*N_*D_];
__device__ __align__(16) __half g_v16[(size_t)B_*H_*N_*D_];
// attention output (split fp16, [B,N,C])
__device__ __align__(16) __half g_xh[(size_t)M_*C_], g_xl[(size_t)M_*C_];

__device__ __forceinline__ float gelu_exact(float x) {
    return 0.5f * x * (1.0f + erff(x * 0.70710678118654752f));
}
__device__ __forceinline__ uint32_t smem_u32(const void* p) {
    uint32_t a;
    asm("{ .reg .u64 t; cvta.to.shared.u64 t, %1; cvt.u32.u64 %0, t; }" : "=r"(a) : "l"(p));
    return a;
}
__device__ __forceinline__ uint32_t packh(__half a, __half b) {
    return (uint32_t)__half_as_ushort(a) | ((uint32_t)__half_as_ushort(b) << 16);
}
// split two fp32 into fp16 hi/lo packed pairs (memory order a, b)
__device__ __forceinline__ void split2_f16(float v0, float v1, uint32_t& hp, uint32_t& lp) {
    __half h0 = __float2half_rn(v0), h1 = __float2half_rn(v1);
    float r0 = v0 - __half2float(h0), r1 = v1 - __half2float(h1);
    hp = packh(h0, h1);
    lp = packh(__float2half_rn(r0), __float2half_rn(r1));
}
#define CVT_F16X2(res, a, b) \
    asm("cvt.rn.f16x2.f32 %0, %1, %2;" : "=r"(res) : "f"(b), "f"(a))

#define LDMATRIX_X4(r0, r1, r2, r3, addr) \
    asm volatile("ldmatrix.sync.aligned.m8n8.x4.shared.b16 {%0,%1,%2,%3}, [%4];" \
        : "=r"(r0), "=r"(r1), "=r"(r2), "=r"(r3) : "r"(addr))
#define LDMATRIX_X4_T(r0, r1, r2, r3, addr) \
    asm volatile("ldmatrix.sync.aligned.m8n8.x4.trans.shared.b16 {%0,%1,%2,%3}, [%4];" \
        : "=r"(r0), "=r"(r1), "=r"(r2), "=r"(r3) : "r"(addr))
#define LDMATRIX_X2(r0, r1, addr) \
    asm volatile("ldmatrix.sync.aligned.m8n8.x2.shared.b16 {%0,%1}, [%2];" \
        : "=r"(r0), "=r"(r1) : "r"(addr))

__device__ __forceinline__ void mma16816h(float* d, uint32_t a0, uint32_t a1,
                                          uint32_t a2, uint32_t a3,
                                          uint32_t b0, uint32_t b1) {
    asm volatile("mma.sync.aligned.m16n8k16.row.col.f32.f16.f16.f32 "
        "{%0,%1,%2,%3}, {%4,%5,%6,%7}, {%8,%9}, {%0,%1,%2,%3};"
        : "+f"(d[0]), "+f"(d[1]), "+f"(d[2]), "+f"(d[3])
        : "r"(a0), "r"(a1), "r"(a2), "r"(a3), "r"(b0), "r"(b1));
}
#define MMA_F16(d, a, b) \
    asm volatile("mma.sync.aligned.m16n8k16.row.col.f32.f16.f16.f32 " \
        "{%0,%1,%2,%3}, {%4,%5,%6,%7}, {%8,%9}, {%0,%1,%2,%3};" \
        : "+f"((d)[0]), "+f"((d)[1]), "+f"((d)[2]), "+f"((d)[3]) \
        : "r"((a)[0]), "r"((a)[1]), "r"((a)[2]), "r"((a)[3]), "r"((b)[0]), "r"((b)[1]))

__device__ __forceinline__ void cp16(uint32_t saddr, const void* g) {
    asm volatile("cp.async.ca.shared.global [%0], [%1], 16;" :: "r"(saddr), "l"(g));
}
#define CP_COMMIT() asm volatile("cp.async.commit_group;" ::: "memory")
#define CP_WAIT(n)  asm volatile("cp.async.wait_group %0;" :: "n"(n) : "memory")

// ------------------------------------------------ fp32 -> split fp16 converter
__global__ void split_h(const float4* __restrict__ in, uint2* __restrict__ hi,
                        uint2* __restrict__ lo, int n4)
{
    int i = blockIdx.x * blockDim.x + threadIdx.x;
    if (i >= n4) return;
    float4 v = in[i];
    uint32_t h01, h23, l01, l23;
    split2_f16(v.x, v.y, h01, l01);
    split2_f16(v.z, v.w, h23, l23);
    hi[i] = make_uint2(h01, h23);
    lo[i] = make_uint2(l01, l23);
}

// ------------------------------------------------------------ HMMA projection
// Operands pre-split fp16, 3-pass (hh + h·lo + lo·h). Tile 128x128, BK=32.
// OUT_MODE: 0 = fp32 [M][C], 1 = split fp16 head-major, 2 = single fp16 head-major
#define PROW 80
#define PTILE 10240
#define PSTAGE 40960
#define PROJ_SMEM 81920

template<int DO_BIAS, int DO_GELU, int DO_SCALE, int OUT_MODE>
__global__ __launch_bounds__(256, 2)
void proj2(const __half* __restrict__ Xh, const __half* __restrict__ Xl,
           const __half* __restrict__ Wh, const __half* __restrict__ Wl,
           const float* __restrict__ bias, float* __restrict__ outF,
           __half* __restrict__ outH, __half* __restrict__ outL,
           __half* __restrict__ outV)
{
    extern __shared__ __align__(16) char sm[];
    const uint32_t sb = smem_u32(sm);

    const int m0 = blockIdx.y * 128;
    const int n0 = blockIdx.x * 128;
    const int tid = threadIdx.x;
    const int lane = tid & 31;
    const int warp = tid >> 5;
    const int wm = warp & 1;
    const int wn = warp >> 1;

    const char* src[4] = {
        (const char*)(Xh + (size_t)m0 * C_), (const char*)(Xl + (size_t)m0 * C_),
        (const char*)(Wh + (size_t)n0 * C_), (const char*)(Wl + (size_t)n0 * C_) };

    float acc[4][4][4];
    #pragma unroll
    for (int i = 0; i < 4; i++)
        #pragma unroll
        for (int j = 0; j < 4; j++)
            #pragma unroll
            for (int e = 0; e < 4; e++) acc[i][j][e] = 0.f;

    #pragma unroll
    for (int u = 0; u < 8; u++) {
        int idx = u * 256 + tid;
        int arr = idx >> 9, rem = idx & 511;
        int row = rem >> 2, ch = rem & 3;
        cp16(sb + arr * PTILE + row * PROW + ch * 16,
             src[arr] + (size_t)row * (C_ * 2) + ch * 16);
    }
    CP_COMMIT();

    for (int kc = 0; kc < C_ / 32; kc++) {
        const int st = kc & 1;
        CP_WAIT(0);
        __syncthreads();
        if (kc + 1 < C_ / 32) {
            const uint32_t dbase = sb + (st ^ 1) * PSTAGE;
            const int k0b = (kc + 1) * 64;
            #pragma unroll
            for (int u = 0; u < 8; u++) {
                int idx = u * 256 + tid;
                int arr = idx >> 9, rem = idx & 511;
                int row = rem >> 2, ch = rem & 3;
                cp16(dbase + arr * PTILE + row * PROW + ch * 16,
                     src[arr] + (size_t)row * (C_ * 2) + k0b + ch * 16);
            }
            CP_COMMIT();
        }

        const uint32_t abase = sb + st * PSTAGE;
        const uint32_t aHi = abase + (wm * 64 + (lane & 15)) * PROW + ((lane >> 4) << 4);
        const uint32_t aLo = aHi + PTILE;
        const uint32_t bHi = abase + 2 * PTILE + (wn * 32 + (lane & 7)) * PROW + (((lane >> 3) & 1) << 4);
        const uint32_t bLo = bHi + PTILE;

        #pragma unroll
        for (int ks = 0; ks < 2; ks++) {
            const uint32_t koff = ks * 32;
            uint32_t ahi[4][4], alo[4][4], bhi[4][2], blo[4][2];
            #pragma unroll
            for (int mi = 0; mi < 4; mi++) {
                uint32_t ofs = mi * 16 * PROW + koff;
                LDMATRIX_X4(ahi[mi][0], ahi[mi][1], ahi[mi][2], ahi[mi][3], aHi + ofs);
                LDMATRIX_X4(alo[mi][0], alo[mi][1], alo[mi][2], alo[mi][3], aLo + ofs);
            }
            #pragma unroll
            for (int ni = 0; ni < 4; ni++) {
                uint32_t ofs = ni * 8 * PROW + koff;
                LDMATRIX_X2(bhi[ni][0], bhi[ni][1], bHi + ofs);
                LDMATRIX_X2(blo[ni][0], blo[ni][1], bLo + ofs);
            }
            #pragma unroll
            for (int mi = 0; mi < 4; mi++)
                #pragma unroll
                for (int ni = 0; ni < 4; ni++) {
                    MMA_F16(acc[mi][ni], ahi[mi], bhi[ni]);
                    MMA_F16(acc[mi][ni], ahi[mi], blo[ni]);
                    MMA_F16(acc[mi][ni], alo[mi], bhi[ni]);
                }
        }
    }

    #pragma unroll
    for (int mi = 0; mi < 4; mi++)
        #pragma unroll
        for (int ni = 0; ni < 4; ni++)
            #pragma unroll
            for (int ep = 0; ep < 2; ep++) {
                int m = m0 + wm * 64 + mi * 16 + (lane >> 2) + ep * 8;
                int n = n0 + wn * 32 + ni * 8 + (lane & 3) * 2;
                float v0 = acc[mi][ni][ep * 2 + 0];
                float v1 = acc[mi][ni][ep * 2 + 1];
                if (DO_BIAS) { v0 += bias[n]; v1 += bias[n + 1]; }
                if (DO_GELU) { v0 = gelu_exact(v0); v1 = gelu_exact(v1); }
                if (DO_SCALE) { v0 *= SCALE_; v1 *= SCALE_; }
                if (OUT_MODE == 1 || OUT_MODE == 2) {
                    int bb = m >> 12, nr = m & (N_ - 1);
                    int h = n >> 6, d = n & 63;
                    size_t eidx = ((((size_t)(bb * H_ + h)) * N_ + nr) * D_ + d);
                    if (OUT_MODE == 1) {
                        uint32_t hp, lp;
                        split2_f16(v0, v1, hp, lp);
                        *(uint32_t*)((char*)outH + eidx * 2) = hp;
                        *(uint32_t*)((char*)outL + eidx * 2) = lp;
                    } else {
                        uint32_t vp;
                        CVT_F16X2(vp, v0, v1);
                        *(uint32_t*)((char*)outV + eidx * 2) = vp;
                    }
                } else {
                    *(float2*)(outF + (size_t)m * C_ + n) = make_float2(v0, v1);
                }
            }
}

// ------------------------------------------------- HMMA flash attention
// QK^T: 2-pass (qh·kh + qh·kl), Q single fp16 pre-scaled. P·V: single-pass fp16.
#define APB 144
#define SQ 0
#define SBUF0 (128*APB)               // 18432
#define STILE (64*APB)                // 9216
#define SBUFSZ (3*STILE)              // 27648 (Kh, Kl, V)
#define ATT_SMEM (SBUF0 + 2*SBUFSZ)   // 73728

__global__ __launch_bounds__(256, 2)
void attn_mma(__half* __restrict__ pxh, __half* __restrict__ pxl)
{
    extern __shared__ __align__(16) char sm[];
    const uint32_t sb = smem_u32(sm);

    const int bh = blockIdx.y;
    const int b  = bh / H_, h = bh - b * H_;
    const int q0 = blockIdx.x * 128;
    const int tid = threadIdx.x;
    const int lane = tid & 31;
    const int w = tid >> 5;

    const char* Qg = (const char*)(g_q16 + ((size_t)bh * N_ + q0) * D_);
    const char* src[3] = {
        (const char*)(g_kh + (size_t)bh * N_ * D_),
        (const char*)(g_kl + (size_t)bh * N_ * D_),
        (const char*)(g_v16 + (size_t)bh * N_ * D_) };

    // group A: Q tile (128 rows x 8 chunks)
    #pragma unroll
    for (int i = 0; i < 4; i++) {
        int idx = i * 256 + tid;
        int row = idx >> 3, ch = idx & 7;
        cp16(sb + SQ + row * APB + ch * 16, Qg + row * 128 + ch * 16);
    }
    CP_COMMIT();
    // group B: K/V tile 0
    #pragma unroll
    for (int i = 0; i < 6; i++) {
        int idx = i * 256 + tid;
        int arr = idx >> 9, rem = idx & 511;
        int row = rem >> 3, ch = rem & 7;
        cp16(sb + SBUF0 + arr * STILE + row * APB + ch * 16,
             src[arr] + (size_t)row * 128 + ch * 16);
    }
    CP_COMMIT();

    // hoist Q fragments to registers (reused all 64 iterations)
    CP_WAIT(1);
    __syncthreads();
    const int wq = w * 16;
    const uint32_t aQ = sb + SQ + (wq + (lane & 15)) * APB + ((lane >> 4) << 4);
    uint32_t qf[4][4];
    #pragma unroll
    for (int ks = 0; ks < 4; ks++)
        LDMATRIX_X4(qf[ks][0], qf[ks][1], qf[ks][2], qf[ks][3], aQ + ks * 32);

    float o[8][4];
    #pragma unroll
    for (int g = 0; g < 8; g++)
        #pragma unroll
        for (int e = 0; e < 4; e++) o[g][e] = 0.f;
    float mA = -1e30f, mB = -1e30f, lA = 0.f, lB = 0.f;

    const uint32_t rowsel = (lane & 15) * APB + ((lane >> 4) << 4);

    for (int t = 0; t < 64; t++) {
        const int buf = t & 1;
        CP_WAIT(0);
        __syncthreads();
        if (t + 1 < 64) {
            const uint32_t dbase = sb + SBUF0 + (1 - buf) * SBUFSZ;
            const size_t gofs = (size_t)(t + 1) * 64 * 128;
            #pragma unroll
            for (int i = 0; i < 6; i++) {
                int idx = i * 256 + tid;
                int arr = idx >> 9, rem = idx & 511;
                int row = rem >> 3, ch = rem & 7;
                cp16(dbase + arr * STILE + row * APB + ch * 16,
                     src[arr] + gofs + (size_t)row * 128 + ch * 16);
            }
            CP_COMMIT();
        }

        const uint32_t sKh = sb + SBUF0 + buf * SBUFSZ;
        const uint32_t sKl = sKh + STILE;
        const uint32_t sV  = sKh + 2 * STILE;

        // ---- S = QK^T (2-pass: qh·kh + qh·kl)
        float s[8][4];
        #pragma unroll
        for (int f = 0; f < 8; f++)
            #pragma unroll
            for (int e = 0; e < 4; e++) s[f][e] = 0.f;

        #pragma unroll
        for (int ks = 0; ks < 4; ks++) {
            #pragma unroll
            for (int p = 0; p < 4; p++) {
                uint32_t kh0, kh1, kh2, kh3, kl0, kl1, kl2, kl3;
                LDMATRIX_X4(kh0, kh1, kh2, kh3, sKh + (16 * p) * APB + rowsel + ks * 32);
                LDMATRIX_X4(kl0, kl1, kl2, kl3, sKl + (16 * p) * APB + rowsel + ks * 32);
                mma16816h(s[2*p],   qf[ks][0], qf[ks][1], qf[ks][2], qf[ks][3], kh0, kh2);
                mma16816h(s[2*p+1], qf[ks][0], qf[ks][1], qf[ks][2], qf[ks][3], kh1, kh3);
                mma16816h(s[2*p],   qf[ks][0], qf[ks][1], qf[ks][2], qf[ks][3], kl0, kl2);
                mma16816h(s[2*p+1], qf[ks][0], qf[ks][1], qf[ks][2], qf[ks][3], kl1, kl3);
            }
        }

        // ---- online softmax (rows: A = lane>>2, B = A+8)
        float mxA = -1e30f, mxB = -1e30f;
        #pragma unroll
        for (int f = 0; f < 8; f++) {
            mxA = fmaxf(mxA, fmaxf(s[f][0], s[f][1]));
            mxB = fmaxf(mxB, fmaxf(s[f][2], s[f][3]));
        }
        mxA = fmaxf(mxA, __shfl_xor_sync(0xffffffffu, mxA, 1, 4));
        mxA = fmaxf(mxA, __shfl_xor_sync(0xffffffffu, mxA, 2, 4));
        mxB = fmaxf(mxB, __shfl_xor_sync(0xffffffffu, mxB, 1, 4));
        mxB = fmaxf(mxB, __shfl_xor_sync(0xffffffffu, mxB, 2, 4));
        float mnA = fmaxf(mA, mxA), mnB = fmaxf(mB, mxB);
        float alA = __expf(mA - mnA), alB = __expf(mB - mnB);
        mA = mnA; mB = mnB;
        float suA = 0.f, suB = 0.f;
        #pragma unroll
        for (int f = 0; f < 8; f++) {
            s[f][0] = __expf(s[f][0] - mnA); suA += s[f][0];
            s[f][1] = __expf(s[f][1] - mnA); suA += s[f][1];
            s[f][2] = __expf(s[f][2] - mnB); suB += s[f][2];
            s[f][3] = __expf(s[f][3] - mnB); suB += s[f][3];
        }
        suA += __shfl_xor_sync(0xffffffffu, suA, 1, 4);
        suA += __shfl_xor_sync(0xffffffffu, suA, 2, 4);
        suB += __shfl_xor_sync(0xffffffffu, suB, 1, 4);
        suB += __shfl_xor_sync(0xffffffffu, suB, 2, 4);
        lA = lA * alA + suA;
        lB = lB * alB + suB;
        #pragma unroll
        for (int g = 0; g < 8; g++) {
            o[g][0] *= alA; o[g][1] *= alA;
            o[g][2] *= alB; o[g][3] *= alB;
        }

        // ---- O += P @ V  (single-pass fp16)
        #pragma unroll
        for (int kt = 0; kt < 4; kt++) {
            uint32_t ph0, ph1, ph2, ph3;
            CVT_F16X2(ph0, s[2*kt][0],   s[2*kt][1]);
            CVT_F16X2(ph1, s[2*kt][2],   s[2*kt][3]);
            CVT_F16X2(ph2, s[2*kt+1][0], s[2*kt+1][1]);
            CVT_F16X2(ph3, s[2*kt+1][2], s[2*kt+1][3]);
            #pragma unroll
            for (int g = 0; g < 4; g++) {
                uint32_t vh0, vh1, vh2, vh3;
                LDMATRIX_X4_T(vh0, vh1, vh2, vh3, sV + (16 * kt) * APB + rowsel + g * 32);
                mma16816h(o[2*g],   ph0, ph1, ph2, ph3, vh0, vh1);
                mma16816h(o[2*g+1], ph0, ph1, ph2, ph3, vh2, vh3);
            }
        }
    }

    // ---- normalize + write split fp16 [B,N,C]
    const float ivA = 1.f / lA, ivB = 1.f / lB;
    const int rowA = q0 + wq + (lane >> 2);
    const int col0 = h * D_ + 2 * (lane & 3);
    #pragma unroll
    for (int g = 0; g < 8; g++) {
        uint32_t hp, lp;
        split2_f16(o[g][0] * ivA, o[g][1] * ivA, hp, lp);
        size_t e = (size_t)(b * N_ + rowA) * C_ + col0 + 8 * g;
        *(uint32_t*)((char*)pxh + e * 2) = hp;
        *(uint32_t*)((char*)pxl + e * 2) = lp;

        split2_f16(o[g][2] * ivB, o[g][3] * ivB, hp, lp);
        e = (size_t)(b * N_ + rowA + 8) * C_ + col0 + 8 * g;
        *(uint32_t*)((char*)pxh + e * 2) = hp;
        *(uint32_t*)((char*)pxl + e * 2) = lp;
    }
}

extern "C" void kernel_launch(void* const* d_in, const int* in_sizes, int n_in,
                              void* d_out, int out_size)
{
    const float* query = (const float*)d_in[0];
    const float* key   = (const float*)d_in[1];
    const float* value = (const float*)d_in[2];
    const float* Wq    = (const float*)d_in[3];
    const float* Wk    = (const float*)d_in[4];
    const float* bk    = (const float*)d_in[5];
    const float* Wv    = (const float*)d_in[6];
    const float* Wp    = (const float*)d_in[7];
    const float* bp    = (const float*)d_in[8];
    float* out = (float*)d_out;

    #define GA(sym) ({ void* _p; cudaGetSymbolAddress(&_p, sym); _p; })
    __half *iqh = (__half*)GA(g_iqh), *iql = (__half*)GA(g_iql);
    __half *ikh = (__half*)GA(g_ikh), *ikl = (__half*)GA(g_ikl);
    __half *ivh = (__half*)GA(g_ivh), *ivl = (__half*)GA(g_ivl);
    __half *wqh = (__half*)GA(g_wqh), *wql = (__half*)GA(g_wql);
    __half *wkh = (__half*)GA(g_wkh), *wkl = (__half*)GA(g_wkl);
    __half *wvh = (__half*)GA(g_wvh), *wvl = (__half*)GA(g_wvl);
    __half *wph = (__half*)GA(g_wph), *wpl = (__half*)GA(g_wpl);
    __half *pq  = (__half*)GA(g_q16);
    __half *pkh = (__half*)GA(g_kh),  *pkl = (__half*)GA(g_kl);
    __half *pv  = (__half*)GA(g_v16);
    __half *pxh = (__half*)GA(g_xh),  *pxl = (__half*)GA(g_xl);

    static bool attr_done = false;
    if (!attr_done) {
        cudaFuncSetAttribute(proj2<0,0,1,2>, cudaFuncAttributeMaxDynamicSharedMemorySize, PROJ_SMEM);
        cudaFuncSetAttribute(proj2<1,1,0,1>, cudaFuncAttributeMaxDynamicSharedMemorySize, PROJ_SMEM);
        cudaFuncSetAttribute(proj2<0,0,0,2>, cudaFuncAttributeMaxDynamicSharedMemorySize, PROJ_SMEM);
        cudaFuncSetAttribute(proj2<1,0,0,0>, cudaFuncAttributeMaxDynamicSharedMemorySize, PROJ_SMEM);
        cudaFuncSetAttribute(attn_mma, cudaFuncAttributeMaxDynamicSharedMemorySize, ATT_SMEM);
        attr_done = true;
    }

    const int nx4 = M_ * C_ / 4;
    const int nw4 = C_ * C_ / 4;
    split_h<<<(nx4 + 255) / 256, 256>>>((const float4*)query, (uint2*)iqh, (uint2*)iql, nx4);
    split_h<<<(nx4 + 255) / 256, 256>>>((const float4*)key,   (uint2*)ikh, (uint2*)ikl, nx4);
    split_h<<<(nx4 + 255) / 256, 256>>>((const float4*)value, (uint2*)ivh, (uint2*)ivl, nx4);
    split_h<<<(nw4 + 255) / 256, 256>>>((const float4*)Wq, (uint2*)wqh, (uint2*)wql, nw4);
    split_h<<<(nw4 + 255) / 256, 256>>>((const float4*)Wk, (uint2*)wkh, (uint2*)wkl, nw4);
    split_h<<<(nw4 + 255) / 256, 256>>>((const float4*)Wv, (uint2*)wvh, (uint2*)wvl, nw4);
    split_h<<<(nw4 + 255) / 256, 256>>>((const float4*)Wp, (uint2*)wph, (uint2*)wpl, nw4);

    dim3 gp(6, 64);
    proj2<0,0,1,2><<<gp, 256, PROJ_SMEM>>>(iqh, iql, wqh, wql, nullptr, nullptr, nullptr, nullptr, pq);
    proj2<1,1,0,1><<<gp, 256, PROJ_SMEM>>>(ikh, ikl, wkh, wkl, bk,      nullptr, pkh, pkl, nullptr);
    proj2<0,0,0,2><<<gp, 256, PROJ_SMEM>>>(ivh, ivl, wvh, wvl, nullptr, nullptr, nullptr, nullptr, pv);

    attn_mma<<<dim3(32, 24), 256, ATT_SMEM>>>(pxh, pxl);

    proj2<1,0,0,0><<<gp, 256, PROJ_SMEM>>>(pxh, pxl, wph, wpl, bp, out, nullptr, nullptr, nullptr);
}

// round 8
// speedup vs baseline: 5.9176x; 1.5317x over previous
#include <cuda_runtime.h>
#include <cuda_fp16.h>
#include <math.h>
#include <stdint.h>

#define B_ 2
#define N_ 4096
#define C_ 768
#define H_ 12
#define D_ 64
#define M_ (B_*N_)
// 0.125 * log2(e): folded into Q so softmax can use exp2f
#define QSC_ 0.18033688f

// ---- scratch (allocation-free) ----
__device__ __align__(16) __half g_iq[(size_t)M_*C_], g_ik[(size_t)M_*C_], g_iv[(size_t)M_*C_];
__device__ __align__(16) __half g_wq[(size_t)C_*C_], g_wk[(size_t)C_*C_], g_wv[(size_t)C_*C_];
__device__ __align__(16) __half g_wph[(size_t)C_*C_], g_wpl[(size_t)C_*C_];
// projections, head-major [B,H,N,D], all single fp16 (Q pre-scaled by QSC_)
__device__ __align__(16) __half g_q16[(size_t)B_*H_*N_*D_];
__device__ __align__(16) __half g_k16[(size_t)B_*H_*N_*D_];
__device__ __align__(16) __half g_v16[(size_t)B_*H_*N_*D_];
// attention output fp16 [B,N,C]
__device__ __align__(16) __half g_x16[(size_t)M_*C_];

__device__ __forceinline__ float gelu_exact(float x) {
    return 0.5f * x * (1.0f + erff(x * 0.70710678118654752f));
}
__device__ __forceinline__ uint32_t smem_u32(const void* p) {
    uint32_t a;
    asm("{ .reg .u64 t; cvta.to.shared.u64 t, %1; cvt.u32.u64 %0, t; }" : "=r"(a) : "l"(p));
    return a;
}
#define CVT_F16X2(res, a, b) \
    asm("cvt.rn.f16x2.f32 %0, %1, %2;" : "=r"(res) : "f"(b), "f"(a))
__device__ __forceinline__ uint32_t packh(__half a, __half b) {
    return (uint32_t)__half_as_ushort(a) | ((uint32_t)__half_as_ushort(b) << 16);
}
__device__ __forceinline__ void split2_f16(float v0, float v1, uint32_t& hp, uint32_t& lp) {
    __half h0 = __float2half_rn(v0), h1 = __float2half_rn(v1);
    float r0 = v0 - __half2float(h0), r1 = v1 - __half2float(h1);
    hp = packh(h0, h1);
    lp = packh(__float2half_rn(r0), __float2half_rn(r1));
}

#define LDMATRIX_X4(r0, r1, r2, r3, addr) \
    asm volatile("ldmatrix.sync.aligned.m8n8.x4.shared.b16 {%0,%1,%2,%3}, [%4];" \
        : "=r"(r0), "=r"(r1), "=r"(r2), "=r"(r3) : "r"(addr))
#define LDMATRIX_X4_T(r0, r1, r2, r3, addr) \
    asm volatile("ldmatrix.sync.aligned.m8n8.x4.trans.shared.b16 {%0,%1,%2,%3}, [%4];" \
        : "=r"(r0), "=r"(r1), "=r"(r2), "=r"(r3) : "r"(addr))
#define LDMATRIX_X2(r0, r1, addr) \
    asm volatile("ldmatrix.sync.aligned.m8n8.x2.shared.b16 {%0,%1}, [%2];" \
        : "=r"(r0), "=r"(r1) : "r"(addr))

__device__ __forceinline__ void mma16816h(float* d, uint32_t a0, uint32_t a1,
                                          uint32_t a2, uint32_t a3,
                                          uint32_t b0, uint32_t b1) {
    asm volatile("mma.sync.aligned.m16n8k16.row.col.f32.f16.f16.f32 "
        "{%0,%1,%2,%3}, {%4,%5,%6,%7}, {%8,%9}, {%0,%1,%2,%3};"
        : "+f"(d[0]), "+f"(d[1]), "+f"(d[2]), "+f"(d[3])
        : "r"(a0), "r"(a1), "r"(a2), "r"(a3), "r"(b0), "r"(b1));
}
#define MMA_F16(d, a, b) \
    asm volatile("mma.sync.aligned.m16n8k16.row.col.f32.f16.f16.f32 " \
        "{%0,%1,%2,%3}, {%4,%5,%6,%7}, {%8,%9}, {%0,%1,%2,%3};" \
        : "+f"((d)[0]), "+f"((d)[1]), "+f"((d)[2]), "+f"((d)[3]) \
        : "r"((a)[0]), "r"((a)[1]), "r"((a)[2]), "r"((a)[3]), "r"((b)[0]), "r"((b)[1]))

__device__ __forceinline__ void cp16(uint32_t saddr, const void* g) {
    asm volatile("cp.async.ca.shared.global [%0], [%1], 16;" :: "r"(saddr), "l"(g));
}
#define CP_COMMIT() asm volatile("cp.async.commit_group;" ::: "memory")
#define CP_WAIT(n)  asm volatile("cp.async.wait_group %0;" :: "n"(n) : "memory")

// ------------------------------------------------ converters
__global__ void cvt_h(const float4* __restrict__ in, uint2* __restrict__ out, int n4)
{
    int i = blockIdx.x * blockDim.x + threadIdx.x;
    if (i >= n4) return;
    float4 v = in[i];
    uint32_t a, b;
    CVT_F16X2(a, v.x, v.y);
    CVT_F16X2(b, v.z, v.w);
    out[i] = make_uint2(a, b);
}
__global__ void split_h(const float4* __restrict__ in, uint2* __restrict__ hi,
                        uint2* __restrict__ lo, int n4)
{
    int i = blockIdx.x * blockDim.x + threadIdx.x;
    if (i >= n4) return;
    float4 v = in[i];
    uint32_t h01, h23, l01, l23;
    split2_f16(v.x, v.y, h01, l01);
    split2_f16(v.z, v.w, h23, l23);
    hi[i] = make_uint2(h01, h23);
    lo[i] = make_uint2(l01, l23);
}

// --------------------------------------- 1-pass fp16 projection (Q/K/V)
// out[m][n] = sum_k X[m][k]*W[n][k] (+bias,+gelu,*qscale) -> fp16 head-major
#define PROW 80
#define PTILE 10240
#define ASTAGE 20480          // X tile + W tile

template<int DO_BIAS, int DO_GELU, int DO_QSCALE>
__global__ __launch_bounds__(256, 2)
void projA(const __half* __restrict__ X, const __half* __restrict__ W,
           const float* __restrict__ bias, __half* __restrict__ outV)
{
    __shared__ __align__(16) char sm[2 * ASTAGE];
    const uint32_t sb = smem_u32(sm);

    const int m0 = blockIdx.y * 128;
    const int n0 = blockIdx.x * 128;
    const int tid = threadIdx.x;
    const int lane = tid & 31;
    const int warp = tid >> 5;
    const int wm = warp & 1;
    const int wn = warp >> 1;

    const char* src[2] = {
        (const char*)(X + (size_t)m0 * C_), (const char*)(W + (size_t)n0 * C_) };

    float acc[4][4][4];
    #pragma unroll
    for (int i = 0; i < 4; i++)
        #pragma unroll
        for (int j = 0; j < 4; j++)
            #pragma unroll
            for (int e = 0; e < 4; e++) acc[i][j][e] = 0.f;

    #pragma unroll
    for (int u = 0; u < 4; u++) {
        int idx = u * 256 + tid;
        int arr = idx >> 9, rem = idx & 511;
        int row = rem >> 2, ch = rem & 3;
        cp16(sb + arr * PTILE + row * PROW + ch * 16,
             src[arr] + (size_t)row * (C_ * 2) + ch * 16);
    }
    CP_COMMIT();

    for (int kc = 0; kc < C_ / 32; kc++) {
        const int st = kc & 1;
        CP_WAIT(0);
        __syncthreads();
        if (kc + 1 < C_ / 32) {
            const uint32_t dbase = sb + (st ^ 1) * ASTAGE;
            const int k0b = (kc + 1) * 64;
            #pragma unroll
            for (int u = 0; u < 4; u++) {
                int idx = u * 256 + tid;
                int arr = idx >> 9, rem = idx & 511;
                int row = rem >> 2, ch = rem & 3;
                cp16(dbase + arr * PTILE + row * PROW + ch * 16,
                     src[arr] + (size_t)row * (C_ * 2) + k0b + ch * 16);
            }
            CP_COMMIT();
        }

        const uint32_t abase = sb + st * ASTAGE;
        const uint32_t aA = abase + (wm * 64 + (lane & 15)) * PROW + ((lane >> 4) << 4);
        const uint32_t bA = abase + PTILE + (wn * 32 + (lane & 7)) * PROW + (((lane >> 3) & 1) << 4);

        #pragma unroll
        for (int ks = 0; ks < 2; ks++) {
            const uint32_t koff = ks * 32;
            uint32_t af[4][4], bf[4][2];
            #pragma unroll
            for (int mi = 0; mi < 4; mi++)
                LDMATRIX_X4(af[mi][0], af[mi][1], af[mi][2], af[mi][3],
                            aA + mi * 16 * PROW + koff);
            #pragma unroll
            for (int ni = 0; ni < 4; ni++)
                LDMATRIX_X2(bf[ni][0], bf[ni][1], bA + ni * 8 * PROW + koff);
            #pragma unroll
            for (int mi = 0; mi < 4; mi++)
                #pragma unroll
                for (int ni = 0; ni < 4; ni++)
                    MMA_F16(acc[mi][ni], af[mi], bf[ni]);
        }
    }

    #pragma unroll
    for (int mi = 0; mi < 4; mi++)
        #pragma unroll
        for (int ni = 0; ni < 4; ni++)
            #pragma unroll
            for (int ep = 0; ep < 2; ep++) {
                int m = m0 + wm * 64 + mi * 16 + (lane >> 2) + ep * 8;
                int n = n0 + wn * 32 + ni * 8 + (lane & 3) * 2;
                float v0 = acc[mi][ni][ep * 2 + 0];
                float v1 = acc[mi][ni][ep * 2 + 1];
                if (DO_BIAS) { v0 += bias[n]; v1 += bias[n + 1]; }
                if (DO_GELU) { v0 = gelu_exact(v0); v1 = gelu_exact(v1); }
                if (DO_QSCALE) { v0 *= QSC_; v1 *= QSC_; }
                int bb = m >> 12, nr = m & (N_ - 1);
                int h = n >> 6, d = n & 63;
                size_t eidx = ((((size_t)(bb * H_ + h)) * N_ + nr) * D_ + d);
                uint32_t vp;
                CVT_F16X2(vp, v0, v1);
                *(uint32_t*)((char*)outV + eidx * 2) = vp;
            }
}

// --------------------------------------- 2-pass final projection (x @ Wp + bp)
// X single fp16, W split fp16 (hi+lo). fp32 output.
#define PSTG3 30720
#define PROJP_SMEM 61440

__global__ __launch_bounds__(256, 2)
void projP(const __half* __restrict__ X, const __half* __restrict__ Wh,
           const __half* __restrict__ Wl, const float* __restrict__ bias,
           float* __restrict__ outF)
{
    extern __shared__ __align__(16) char sm[];
    const uint32_t sb = smem_u32(sm);

    const int m0 = blockIdx.y * 128;
    const int n0 = blockIdx.x * 128;
    const int tid = threadIdx.x;
    const int lane = tid & 31;
    const int warp = tid >> 5;
    const int wm = warp & 1;
    const int wn = warp >> 1;

    const char* src[3] = {
        (const char*)(X + (size_t)m0 * C_),
        (const char*)(Wh + (size_t)n0 * C_),
        (const char*)(Wl + (size_t)n0 * C_) };

    float acc[4][4][4];
    #pragma unroll
    for (int i = 0; i < 4; i++)
        #pragma unroll
        for (int j = 0; j < 4; j++)
            #pragma unroll
            for (int e = 0; e < 4; e++) acc[i][j][e] = 0.f;

    #pragma unroll
    for (int u = 0; u < 6; u++) {
        int idx = u * 256 + tid;
        int arr = idx >> 9, rem = idx & 511;
        int row = rem >> 2, ch = rem & 3;
        cp16(sb + arr * PTILE + row * PROW + ch * 16,
             src[arr] + (size_t)row * (C_ * 2) + ch * 16);
    }
    CP_COMMIT();

    for (int kc = 0; kc < C_ / 32; kc++) {
        const int st = kc & 1;
        CP_WAIT(0);
        __syncthreads();
        if (kc + 1 < C_ / 32) {
            const uint32_t dbase = sb + (st ^ 1) * PSTG3;
            const int k0b = (kc + 1) * 64;
            #pragma unroll
            for (int u = 0; u < 6; u++) {
                int idx = u * 256 + tid;
                int arr = idx >> 9, rem = idx & 511;
                int row = rem >> 2, ch = rem & 3;
                cp16(dbase + arr * PTILE + row * PROW + ch * 16,
                     src[arr] + (size_t)row * (C_ * 2) + k0b + ch * 16);
            }
            CP_COMMIT();
        }

        const uint32_t abase = sb + st * PSTG3;
        const uint32_t aA = abase + (wm * 64 + (lane & 15)) * PROW + ((lane >> 4) << 4);
        const uint32_t bH = abase + PTILE + (wn * 32 + (lane & 7)) * PROW + (((lane >> 3) & 1) << 4);
        const uint32_t bL = bH + PTILE;

        #pragma unroll
        for (int ks = 0; ks < 2; ks++) {
            const uint32_t koff = ks * 32;
            uint32_t af[4][4], bh[4][2], bl[4][2];
            #pragma unroll
            for (int mi = 0; mi < 4; mi++)
                LDMATRIX_X4(af[mi][0], af[mi][1], af[mi][2], af[mi][3],
                            aA + mi * 16 * PROW + koff);
            #pragma unroll
            for (int ni = 0; ni < 4; ni++) {
                LDMATRIX_X2(bh[ni][0], bh[ni][1], bH + ni * 8 * PROW + koff);
                LDMATRIX_X2(bl[ni][0], bl[ni][1], bL + ni * 8 * PROW + koff);
            }
            #pragma unroll
            for (int mi = 0; mi < 4; mi++)
                #pragma unroll
                for (int ni = 0; ni < 4; ni++) {
                    MMA_F16(acc[mi][ni], af[mi], bh[ni]);
                    MMA_F16(acc[mi][ni], af[mi], bl[ni]);
                }
        }
    }

    #pragma unroll
    for (int mi = 0; mi < 4; mi++)
        #pragma unroll
        for (int ni = 0; ni < 4; ni++)
            #pragma unroll
            for (int ep = 0; ep < 2; ep++) {
                int m = m0 + wm * 64 + mi * 16 + (lane >> 2) + ep * 8;
                int n = n0 + wn * 32 + ni * 8 + (lane & 3) * 2;
                float v0 = acc[mi][ni][ep * 2 + 0] + bias[n];
                float v1 = acc[mi][ni][ep * 2 + 1] + bias[n + 1];
                *(float2*)(outF + (size_t)m * C_ + n) = make_float2(v0, v1);
            }
}

// ------------------------------------------------- HMMA flash attention
// QK^T single-pass fp16 (Q pre-scaled by 0.125*log2e -> exp2f softmax).
// P·V single-pass fp16. 2-stage cp.async on K/V.
#define APB 144
#define SQ 0
#define SBUF0 (128*APB)               // 18432
#define STILE (64*APB)                // 9216
#define SBUFSZ (2*STILE)              // 18432 (K, V)
#define ATT_SMEM (SBUF0 + 2*SBUFSZ)   // 55296

__global__ __launch_bounds__(256, 2)
void attn_mma(__half* __restrict__ px)
{
    extern __shared__ __align__(16) char sm[];
    const uint32_t sb = smem_u32(sm);

    const int bh = blockIdx.y;
    const int b  = bh / H_, h = bh - b * H_;
    const int q0 = blockIdx.x * 128;
    const int tid = threadIdx.x;
    const int lane = tid & 31;
    const int w = tid >> 5;

    const char* Qg = (const char*)(g_q16 + ((size_t)bh * N_ + q0) * D_);
    const char* src[2] = {
        (const char*)(g_k16 + (size_t)bh * N_ * D_),
        (const char*)(g_v16 + (size_t)bh * N_ * D_) };

    // group A: Q tile
    #pragma unroll
    for (int i = 0; i < 4; i++) {
        int idx = i * 256 + tid;
        int row = idx >> 3, ch = idx & 7;
        cp16(sb + SQ + row * APB + ch * 16, Qg + row * 128 + ch * 16);
    }
    CP_COMMIT();
    // group B: K/V tile 0
    #pragma unroll
    for (int i = 0; i < 4; i++) {
        int idx = i * 256 + tid;
        int arr = idx >> 9, rem = idx & 511;
        int row = rem >> 3, ch = rem & 7;
        cp16(sb + SBUF0 + arr * STILE + row * APB + ch * 16,
             src[arr] + (size_t)row * 128 + ch * 16);
    }
    CP_COMMIT();

    // hoist Q fragments
    CP_WAIT(1);
    __syncthreads();
    const int wq = w * 16;
    const uint32_t aQ = sb + SQ + (wq + (lane & 15)) * APB + ((lane >> 4) << 4);
    uint32_t qf[4][4];
    #pragma unroll
    for (int ks = 0; ks < 4; ks++)
        LDMATRIX_X4(qf[ks][0], qf[ks][1], qf[ks][2], qf[ks][3], aQ + ks * 32);

    float o[8][4];
    #pragma unroll
    for (int g = 0; g < 8; g++)
        #pragma unroll
        for (int e = 0; e < 4; e++) o[g][e] = 0.f;
    float mA = -1e30f, mB = -1e30f, lA = 0.f, lB = 0.f;

    const uint32_t rowsel = (lane & 15) * APB + ((lane >> 4) << 4);

    for (int t = 0; t < 64; t++) {
        const int buf = t & 1;
        CP_WAIT(0);
        __syncthreads();
        if (t + 1 < 64) {
            const uint32_t dbase = sb + SBUF0 + (1 - buf) * SBUFSZ;
            const size_t gofs = (size_t)(t + 1) * 64 * 128;
            #pragma unroll
            for (int i = 0; i < 4; i++) {
                int idx = i * 256 + tid;
                int arr = idx >> 9, rem = idx & 511;
                int row = rem >> 3, ch = rem & 7;
                cp16(dbase + arr * STILE + row * APB + ch * 16,
                     src[arr] + gofs + (size_t)row * 128 + ch * 16);
            }
            CP_COMMIT();
        }

        const uint32_t sK = sb + SBUF0 + buf * SBUFSZ;
        const uint32_t sV = sK + STILE;

        // ---- S = QK^T (single-pass fp16; S in log2 units)
        float s[8][4];
        #pragma unroll
        for (int f = 0; f < 8; f++)
            #pragma unroll
            for (int e = 0; e < 4; e++) s[f][e] = 0.f;

        #pragma unroll
        for (int ks = 0; ks < 4; ks++) {
            #pragma unroll
            for (int p = 0; p < 4; p++) {
                uint32_t k0, k1, k2, k3;
                LDMATRIX_X4(k0, k1, k2, k3, sK + (16 * p) * APB + rowsel + ks * 32);
                mma16816h(s[2*p],   qf[ks][0], qf[ks][1], qf[ks][2], qf[ks][3], k0, k2);
                mma16816h(s[2*p+1], qf[ks][0], qf[ks][1], qf[ks][2], qf[ks][3], k1, k3);
            }
        }

        // ---- online softmax in log2 domain (rows: A = lane>>2, B = A+8)
        float mxA = -1e30f, mxB = -1e30f;
        #pragma unroll
        for (int f = 0; f < 8; f++) {
            mxA = fmaxf(mxA, fmaxf(s[f][0], s[f][1]));
            mxB = fmaxf(mxB, fmaxf(s[f][2], s[f][3]));
        }
        mxA = fmaxf(mxA, __shfl_xor_sync(0xffffffffu, mxA, 1, 4));
        mxA = fmaxf(mxA, __shfl_xor_sync(0xffffffffu, mxA, 2, 4));
        mxB = fmaxf(mxB, __shfl_xor_sync(0xffffffffu, mxB, 1, 4));
        mxB = fmaxf(mxB, __shfl_xor_sync(0xffffffffu, mxB, 2, 4));
        float mnA = fmaxf(mA, mxA), mnB = fmaxf(mB, mxB);
        float alA = exp2f(mA - mnA), alB = exp2f(mB - mnB);
        mA = mnA; mB = mnB;
        float suA = 0.f, suB = 0.f;
        #pragma unroll
        for (int f = 0; f < 8; f++) {
            s[f][0] = exp2f(s[f][0] - mnA); suA += s[f][0];
            s[f][1] = exp2f(s[f][1] - mnA); suA += s[f][1];
            s[f][2] = exp2f(s[f][2] - mnB); suB += s[f][2];
            s[f][3] = exp2f(s[f][3] - mnB); suB += s[f][3];
        }
        suA += __shfl_xor_sync(0xffffffffu, suA, 1, 4);
        suA += __shfl_xor_sync(0xffffffffu, suA, 2, 4);
        suB += __shfl_xor_sync(0xffffffffu, suB, 1, 4);
        suB += __shfl_xor_sync(0xffffffffu, suB, 2, 4);
        lA = lA * alA + suA;
        lB = lB * alB + suB;
        #pragma unroll
        for (int g = 0; g < 8; g++) {
            o[g][0] *= alA; o[g][1] *= alA;
            o[g][2] *= alB; o[g][3] *= alB;
        }

        // ---- O += P @ V (single-pass fp16)
        #pragma unroll
        for (int kt = 0; kt < 4; kt++) {
            uint32_t ph0, ph1, ph2, ph3;
            CVT_F16X2(ph0, s[2*kt][0],   s[2*kt][1]);
            CVT_F16X2(ph1, s[2*kt][2],   s[2*kt][3]);
            CVT_F16X2(ph2, s[2*kt+1][0], s[2*kt+1][1]);
            CVT_F16X2(ph3, s[2*kt+1][2], s[2*kt+1][3]);
            #pragma unroll
            for (int g = 0; g < 4; g++) {
                uint32_t v0, v1, v2, v3;
                LDMATRIX_X4_T(v0, v1, v2, v3, sV + (16 * kt) * APB + rowsel + g * 32);
                mma16816h(o[2*g],   ph0, ph1, ph2, ph3, v0, v1);
                mma16816h(o[2*g+1], ph0, ph1, ph2, ph3, v2, v3);
            }
        }
    }

    // ---- normalize + write fp16 [B,N,C]
    const float ivA = 1.f / lA, ivB = 1.f / lB;
    const int rowA = q0 + wq + (lane >> 2);
    const int col0 = h * D_ + 2 * (lane & 3);
    #pragma unroll
    for (int g = 0; g < 8; g++) {
        uint32_t vp;
        CVT_F16X2(vp, o[g][0] * ivA, o[g][1] * ivA);
        size_t e = (size_t)(b * N_ + rowA) * C_ + col0 + 8 * g;
        *(uint32_t*)((char*)px + e * 2) = vp;

        CVT_F16X2(vp, o[g][2] * ivB, o[g][3] * ivB);
        e = (size_t)(b * N_ + rowA + 8) * C_ + col0 + 8 * g;
        *(uint32_t*)((char*)px + e * 2) = vp;
    }
}

extern "C" void kernel_launch(void* const* d_in, const int* in_sizes, int n_in,
                              void* d_out, int out_size)
{
    const float* query = (const float*)d_in[0];
    const float* key   = (const float*)d_in[1];
    const float* value = (const float*)d_in[2];
    const float* Wq    = (const float*)d_in[3];
    const float* Wk    = (const float*)d_in[4];
    const float* bk    = (const float*)d_in[5];
    const float* Wv    = (const float*)d_in[6];
    const float* Wp    = (const float*)d_in[7];
    const float* bp    = (const float*)d_in[8];
    float* out = (float*)d_out;

    #define GA(sym) ({ void* _p; cudaGetSymbolAddress(&_p, sym); _p; })
    __half *iq = (__half*)GA(g_iq), *ik = (__half*)GA(g_ik), *iv = (__half*)GA(g_iv);
    __half *wq = (__half*)GA(g_wq), *wk = (__half*)GA(g_wk), *wv = (__half*)GA(g_wv);
    __half *wph = (__half*)GA(g_wph), *wpl = (__half*)GA(g_wpl);
    __half *pq = (__half*)GA(g_q16), *pk = (__half*)GA(g_k16), *pv = (__half*)GA(g_v16);
    __half *px = (__half*)GA(g_x16);

    static bool attr_done = false;
    if (!attr_done) {
        cudaFuncSetAttribute(projP, cudaFuncAttributeMaxDynamicSharedMemorySize, PROJP_SMEM);
        cudaFuncSetAttribute(attn_mma, cudaFuncAttributeMaxDynamicSharedMemorySize, ATT_SMEM);
        attr_done = true;
    }

    const int nx4 = M_ * C_ / 4;
    const int nw4 = C_ * C_ / 4;
    cvt_h<<<(nx4 + 255) / 256, 256>>>((const float4*)query, (uint2*)iq, nx4);
    cvt_h<<<(nx4 + 255) / 256, 256>>>((const float4*)key,   (uint2*)ik, nx4);
    cvt_h<<<(nx4 + 255) / 256, 256>>>((const float4*)value, (uint2*)iv, nx4);
    cvt_h<<<(nw4 + 255) / 256, 256>>>((const float4*)Wq, (uint2*)wq, nw4);
    cvt_h<<<(nw4 + 255) / 256, 256>>>((const float4*)Wk, (uint2*)wk, nw4);
    cvt_h<<<(nw4 + 255) / 256, 256>>>((const float4*)Wv, (uint2*)wv, nw4);
    split_h<<<(nw4 + 255) / 256, 256>>>((const float4*)Wp, (uint2*)wph, (uint2*)wpl, nw4);

    dim3 gp(6, 64);
    projA<0,0,1><<<gp, 256>>>(iq, wq, nullptr, pq);   // Q: *SCALE*log2e
    projA<1,1,0><<<gp, 256>>>(ik, wk, bk, pk);        // K: +bias, gelu
    projA<0,0,0><<<gp, 256>>>(iv, wv, nullptr, pv);   // V

    attn_mma<<<dim3(32, 24), 256, ATT_SMEM>>>(px);

    projP<<<gp, 256, PROJP_SMEM>>>(px, wph, wpl, bp, out);
}

// round 9
// speedup vs baseline: 6.7173x; 1.1351x over previous
#include <cuda_runtime.h>
#include <cuda_fp16.h>
#include <math.h>
#include <stdint.h>

#define B_ 2
#define N_ 4096
#define C_ 768
#define H_ 12
#define D_ 64
#define M_ (B_*N_)
// 0.125 * log2(e): folded into Q so softmax works in log2 domain
#define QSC_ 0.18033688f
#define ONES2 0x3C003C00u    // half2(1.0, 1.0)

// ---- scratch (allocation-free) ----
__device__ __align__(16) __half g_iq[(size_t)M_*C_], g_ik[(size_t)M_*C_], g_iv[(size_t)M_*C_];
__device__ __align__(16) __half g_wq[(size_t)C_*C_], g_wk[(size_t)C_*C_], g_wv[(size_t)C_*C_];
__device__ __align__(16) __half g_wph[(size_t)C_*C_], g_wpl[(size_t)C_*C_];
__device__ __align__(16) __half g_q16[(size_t)B_*H_*N_*D_];
__device__ __align__(16) __half g_k16[(size_t)B_*H_*N_*D_];
__device__ __align__(16) __half g_v16[(size_t)B_*H_*N_*D_];
__device__ __align__(16) __half g_x16[(size_t)M_*C_];

__device__ __forceinline__ float gelu_exact(float x) {
    return 0.5f * x * (1.0f + erff(x * 0.70710678118654752f));
}
__device__ __forceinline__ uint32_t smem_u32(const void* p) {
    uint32_t a;
    asm("{ .reg .u64 t; cvta.to.shared.u64 t, %1; cvt.u32.u64 %0, t; }" : "=r"(a) : "l"(p));
    return a;
}
#define CVT_F16X2(res, a, b) \
    asm("cvt.rn.f16x2.f32 %0, %1, %2;" : "=r"(res) : "f"(b), "f"(a))
#define EX2_F16X2(r) \
    asm("ex2.approx.f16x2 %0, %0;" : "+r"(r))
__device__ __forceinline__ uint32_t packh(__half a, __half b) {
    return (uint32_t)__half_as_ushort(a) | ((uint32_t)__half_as_ushort(b) << 16);
}
__device__ __forceinline__ void split2_f16(float v0, float v1, uint32_t& hp, uint32_t& lp) {
    __half h0 = __float2half_rn(v0), h1 = __float2half_rn(v1);
    float r0 = v0 - __half2float(h0), r1 = v1 - __half2float(h1);
    hp = packh(h0, h1);
    lp = packh(__float2half_rn(r0), __float2half_rn(r1));
}

#define LDMATRIX_X4(r0, r1, r2, r3, addr) \
    asm volatile("ldmatrix.sync.aligned.m8n8.x4.shared.b16 {%0,%1,%2,%3}, [%4];" \
        : "=r"(r0), "=r"(r1), "=r"(r2), "=r"(r3) : "r"(addr))
#define LDMATRIX_X4_T(r0, r1, r2, r3, addr) \
    asm volatile("ldmatrix.sync.aligned.m8n8.x4.trans.shared.b16 {%0,%1,%2,%3}, [%4];" \
        : "=r"(r0), "=r"(r1), "=r"(r2), "=r"(r3) : "r"(addr))
#define LDMATRIX_X2(r0, r1, addr) \
    asm volatile("ldmatrix.sync.aligned.m8n8.x2.shared.b16 {%0,%1}, [%2];" \
        : "=r"(r0), "=r"(r1) : "r"(addr))

__device__ __forceinline__ void mma16816h(float* d, uint32_t a0, uint32_t a1,
                                          uint32_t a2, uint32_t a3,
                                          uint32_t b0, uint32_t b1) {
    asm volatile("mma.sync.aligned.m16n8k16.row.col.f32.f16.f16.f32 "
        "{%0,%1,%2,%3}, {%4,%5,%6,%7}, {%8,%9}, {%0,%1,%2,%3};"
        : "+f"(d[0]), "+f"(d[1]), "+f"(d[2]), "+f"(d[3])
        : "r"(a0), "r"(a1), "r"(a2), "r"(a3), "r"(b0), "r"(b1));
}
#define MMA_F16(d, a, b) \
    asm volatile("mma.sync.aligned.m16n8k16.row.col.f32.f16.f16.f32 " \
        "{%0,%1,%2,%3}, {%4,%5,%6,%7}, {%8,%9}, {%0,%1,%2,%3};" \
        : "+f"((d)[0]), "+f"((d)[1]), "+f"((d)[2]), "+f"((d)[3]) \
        : "r"((a)[0]), "r"((a)[1]), "r"((a)[2]), "r"((a)[3]), "r"((b)[0]), "r"((b)[1]))

__device__ __forceinline__ void cp16(uint32_t saddr, const void* g) {
    asm volatile("cp.async.ca.shared.global [%0], [%1], 16;" :: "r"(saddr), "l"(g));
}
#define CP_COMMIT() asm volatile("cp.async.commit_group;" ::: "memory")
#define CP_WAIT(n)  asm volatile("cp.async.wait_group %0;" :: "n"(n) : "memory")

// ------------------------------------------------ converters (fused)
__global__ void cvt3(const float4* __restrict__ s0, const float4* __restrict__ s1,
                     const float4* __restrict__ s2, uint2* __restrict__ d0,
                     uint2* __restrict__ d1, uint2* __restrict__ d2, int n4)
{
    int i = blockIdx.x * blockDim.x + threadIdx.x;
    if (i >= n4) return;
    const float4* in = (blockIdx.y == 0) ? s0 : (blockIdx.y == 1) ? s1 : s2;
    uint2* out = (blockIdx.y == 0) ? d0 : (blockIdx.y == 1) ? d1 : d2;
    float4 v = in[i];
    uint32_t a, b;
    CVT_F16X2(a, v.x, v.y);
    CVT_F16X2(b, v.z, v.w);
    out[i] = make_uint2(a, b);
}
__global__ void split_h(const float4* __restrict__ in, uint2* __restrict__ hi,
                        uint2* __restrict__ lo, int n4)
{
    int i = blockIdx.x * blockDim.x + threadIdx.x;
    if (i >= n4) return;
    float4 v = in[i];
    uint32_t h01, h23, l01, l23;
    split2_f16(v.x, v.y, h01, l01);
    split2_f16(v.z, v.w, h23, l23);
    hi[i] = make_uint2(h01, h23);
    lo[i] = make_uint2(l01, l23);
}

// --------------------------------------- fused 1-pass fp16 QKV projection
// blockIdx.z: 0=Q (*QSC_), 1=K (+bias, gelu), 2=V. fp16 head-major out.
#define PROW 80
#define PTILE 10240
#define ASTAGE 20480

__global__ __launch_bounds__(256, 2)
void projQKV(const __half* __restrict__ Xq, const __half* __restrict__ Xk,
             const __half* __restrict__ Xv,
             const __half* __restrict__ Wq, const __half* __restrict__ Wk,
             const __half* __restrict__ Wv,
             const float* __restrict__ bk,
             __half* __restrict__ Oq, __half* __restrict__ Ok, __half* __restrict__ Ov)
{
    __shared__ __align__(16) char sm[2 * ASTAGE];
    const uint32_t sb = smem_u32(sm);

    const int z = blockIdx.z;
    const __half* X = (z == 0) ? Xq : (z == 1) ? Xk : Xv;
    const __half* W = (z == 0) ? Wq : (z == 1) ? Wk : Wv;
    __half* outV    = (z == 0) ? Oq : (z == 1) ? Ok : Ov;

    const int m0 = blockIdx.y * 128;
    const int n0 = blockIdx.x * 128;
    const int tid = threadIdx.x;
    const int lane = tid & 31;
    const int warp = tid >> 5;
    const int wm = warp & 1;
    const int wn = warp >> 1;

    const char* src[2] = {
        (const char*)(X + (size_t)m0 * C_), (const char*)(W + (size_t)n0 * C_) };

    float acc[4][4][4];
    #pragma unroll
    for (int i = 0; i < 4; i++)
        #pragma unroll
        for (int j = 0; j < 4; j++)
            #pragma unroll
            for (int e = 0; e < 4; e++) acc[i][j][e] = 0.f;

    #pragma unroll
    for (int u = 0; u < 4; u++) {
        int idx = u * 256 + tid;
        int arr = idx >> 9, rem = idx & 511;
        int row = rem >> 2, ch = rem & 3;
        cp16(sb + arr * PTILE + row * PROW + ch * 16,
             src[arr] + (size_t)row * (C_ * 2) + ch * 16);
    }
    CP_COMMIT();

    for (int kc = 0; kc < C_ / 32; kc++) {
        const int st = kc & 1;
        CP_WAIT(0);
        __syncthreads();
        if (kc + 1 < C_ / 32) {
            const uint32_t dbase = sb + (st ^ 1) * ASTAGE;
            const int k0b = (kc + 1) * 64;
            #pragma unroll
            for (int u = 0; u < 4; u++) {
                int idx = u * 256 + tid;
                int arr = idx >> 9, rem = idx & 511;
                int row = rem >> 2, ch = rem & 3;
                cp16(dbase + arr * PTILE + row * PROW + ch * 16,
                     src[arr] + (size_t)row * (C_ * 2) + k0b + ch * 16);
            }
            CP_COMMIT();
        }

        const uint32_t abase = sb + st * ASTAGE;
        const uint32_t aA = abase + (wm * 64 + (lane & 15)) * PROW + ((lane >> 4) << 4);
        const uint32_t bA = abase + PTILE + (wn * 32 + (lane & 7)) * PROW + (((lane >> 3) & 1) << 4);

        #pragma unroll
        for (int ks = 0; ks < 2; ks++) {
            const uint32_t koff = ks * 32;
            uint32_t af[4][4], bf[4][2];
            #pragma unroll
            for (int mi = 0; mi < 4; mi++)
                LDMATRIX_X4(af[mi][0], af[mi][1], af[mi][2], af[mi][3],
                            aA + mi * 16 * PROW + koff);
            #pragma unroll
            for (int ni = 0; ni < 4; ni++)
                LDMATRIX_X2(bf[ni][0], bf[ni][1], bA + ni * 8 * PROW + koff);
            #pragma unroll
            for (int mi = 0; mi < 4; mi++)
                #pragma unroll
                for (int ni = 0; ni < 4; ni++)
                    MMA_F16(acc[mi][ni], af[mi], bf[ni]);
        }
    }

    #pragma unroll
    for (int mi = 0; mi < 4; mi++)
        #pragma unroll
        for (int ni = 0; ni < 4; ni++)
            #pragma unroll
            for (int ep = 0; ep < 2; ep++) {
                int m = m0 + wm * 64 + mi * 16 + (lane >> 2) + ep * 8;
                int n = n0 + wn * 32 + ni * 8 + (lane & 3) * 2;
                float v0 = acc[mi][ni][ep * 2 + 0];
                float v1 = acc[mi][ni][ep * 2 + 1];
                if (z == 0) { v0 *= QSC_; v1 *= QSC_; }
                else if (z == 1) {
                    v0 = gelu_exact(v0 + bk[n]);
                    v1 = gelu_exact(v1 + bk[n + 1]);
                }
                int bb = m >> 12, nr = m & (N_ - 1);
                int h = n >> 6, d = n & 63;
                size_t eidx = ((((size_t)(bb * H_ + h)) * N_ + nr) * D_ + d);
                uint32_t vp;
                CVT_F16X2(vp, v0, v1);
                *(uint32_t*)((char*)outV + eidx * 2) = vp;
            }
}

// --------------------------------------- 2-pass final projection (x @ Wp + bp)
#define PSTG3 30720
#define PROJP_SMEM 61440

__global__ __launch_bounds__(256, 2)
void projP(const __half* __restrict__ X, const __half* __restrict__ Wh,
           const __half* __restrict__ Wl, const float* __restrict__ bias,
           float* __restrict__ outF)
{
    extern __shared__ __align__(16) char sm[];
    const uint32_t sb = smem_u32(sm);

    const int m0 = blockIdx.y * 128;
    const int n0 = blockIdx.x * 128;
    const int tid = threadIdx.x;
    const int lane = tid & 31;
    const int warp = tid >> 5;
    const int wm = warp & 1;
    const int wn = warp >> 1;

    const char* src[3] = {
        (const char*)(X + (size_t)m0 * C_),
        (const char*)(Wh + (size_t)n0 * C_),
        (const char*)(Wl + (size_t)n0 * C_) };

    float acc[4][4][4];
    #pragma unroll
    for (int i = 0; i < 4; i++)
        #pragma unroll
        for (int j = 0; j < 4; j++)
            #pragma unroll
            for (int e = 0; e < 4; e++) acc[i][j][e] = 0.f;

    #pragma unroll
    for (int u = 0; u < 6; u++) {
        int idx = u * 256 + tid;
        int arr = idx >> 9, rem = idx & 511;
        int row = rem >> 2, ch = rem & 3;
        cp16(sb + arr * PTILE + row * PROW + ch * 16,
             src[arr] + (size_t)row * (C_ * 2) + ch * 16);
    }
    CP_COMMIT();

    for (int kc = 0; kc < C_ / 32; kc++) {
        const int st = kc & 1;
        CP_WAIT(0);
        __syncthreads();
        if (kc + 1 < C_ / 32) {
            const uint32_t dbase = sb + (st ^ 1) * PSTG3;
            const int k0b = (kc + 1) * 64;
            #pragma unroll
            for (int u = 0; u < 6; u++) {
                int idx = u * 256 + tid;
                int arr = idx >> 9, rem = idx & 511;
                int row = rem >> 2, ch = rem & 3;
                cp16(dbase + arr * PTILE + row * PROW + ch * 16,
                     src[arr] + (size_t)row * (C_ * 2) + k0b + ch * 16);
            }
            CP_COMMIT();
        }

        const uint32_t abase = sb + st * PSTG3;
        const uint32_t aA = abase + (wm * 64 + (lane & 15)) * PROW + ((lane >> 4) << 4);
        const uint32_t bH = abase + PTILE + (wn * 32 + (lane & 7)) * PROW + (((lane >> 3) & 1) << 4);
        const uint32_t bL = bH + PTILE;

        #pragma unroll
        for (int ks = 0; ks < 2; ks++) {
            const uint32_t koff = ks * 32;
            uint32_t af[4][4], bh[4][2], bl[4][2];
            #pragma unroll
            for (int mi = 0; mi < 4; mi++)
                LDMATRIX_X4(af[mi][0], af[mi][1], af[mi][2], af[mi][3],
                            aA + mi * 16 * PROW + koff);
            #pragma unroll
            for (int ni = 0; ni < 4; ni++) {
                LDMATRIX_X2(bh[ni][0], bh[ni][1], bH + ni * 8 * PROW + koff);
                LDMATRIX_X2(bl[ni][0], bl[ni][1], bL + ni * 8 * PROW + koff);
            }
            #pragma unroll
            for (int mi = 0; mi < 4; mi++)
                #pragma unroll
                for (int ni = 0; ni < 4; ni++) {
                    MMA_F16(acc[mi][ni], af[mi], bh[ni]);
                    MMA_F16(acc[mi][ni], af[mi], bl[ni]);
                }
        }
    }

    #pragma unroll
    for (int mi = 0; mi < 4; mi++)
        #pragma unroll
        for (int ni = 0; ni < 4; ni++)
            #pragma unroll
            for (int ep = 0; ep < 2; ep++) {
                int m = m0 + wm * 64 + mi * 16 + (lane >> 2) + ep * 8;
                int n = n0 + wn * 32 + ni * 8 + (lane & 3) * 2;
                float v0 = acc[mi][ni][ep * 2 + 0] + bias[n];
                float v1 = acc[mi][ni][ep * 2 + 1] + bias[n + 1];
                *(float2*)(outF + (size_t)m * C_ + n) = make_float2(v0, v1);
            }
}

// ------------------------------------------------- HMMA flash attention
// QK^T + PV single-pass fp16. Softmax: ex2.approx.f16x2; l via ones-MMA.
#define APB 144
#define SQ 0
#define SBUF0 (128*APB)
#define STILE (64*APB)
#define SBUFSZ (2*STILE)
#define ATT_SMEM (SBUF0 + 2*SBUFSZ)   // 55296

__global__ __launch_bounds__(256, 2)
void attn_mma(__half* __restrict__ px)
{
    extern __shared__ __align__(16) char sm[];
    const uint32_t sb = smem_u32(sm);

    const int bh = blockIdx.y;
    const int b  = bh / H_, h = bh - b * H_;
    const int q0 = blockIdx.x * 128;
    const int tid = threadIdx.x;
    const int lane = tid & 31;
    const int w = tid >> 5;

    const char* Qg = (const char*)(g_q16 + ((size_t)bh * N_ + q0) * D_);
    const char* src[2] = {
        (const char*)(g_k16 + (size_t)bh * N_ * D_),
        (const char*)(g_v16 + (size_t)bh * N_ * D_) };

    #pragma unroll
    for (int i = 0; i < 4; i++) {
        int idx = i * 256 + tid;
        int row = idx >> 3, ch = idx & 7;
        cp16(sb + SQ + row * APB + ch * 16, Qg + row * 128 + ch * 16);
    }
    CP_COMMIT();
    #pragma unroll
    for (int i = 0; i < 4; i++) {
        int idx = i * 256 + tid;
        int arr = idx >> 9, rem = idx & 511;
        int row = rem >> 3, ch = rem & 7;
        cp16(sb + SBUF0 + arr * STILE + row * APB + ch * 16,
             src[arr] + (size_t)row * 128 + ch * 16);
    }
    CP_COMMIT();

    CP_WAIT(1);
    __syncthreads();
    const int wq = w * 16;
    const uint32_t aQ = sb + SQ + (wq + (lane & 15)) * APB + ((lane >> 4) << 4);
    uint32_t qf[4][4];
    #pragma unroll
    for (int ks = 0; ks < 4; ks++)
        LDMATRIX_X4(qf[ks][0], qf[ks][1], qf[ks][2], qf[ks][3], aQ + ks * 32);

    float o[8][4];
    #pragma unroll
    for (int g = 0; g < 8; g++)
        #pragma unroll
        for (int e = 0; e < 4; e++) o[g][e] = 0.f;
    float ol[4] = {0.f, 0.f, 0.f, 0.f};        // ones-column accumulator (l)
    float mA = -1e30f, mB = -1e30f;

    const uint32_t rowsel = (lane & 15) * APB + ((lane >> 4) << 4);

    for (int t = 0; t < 64; t++) {
        const int buf = t & 1;
        CP_WAIT(0);
        __syncthreads();
        if (t + 1 < 64) {
            const uint32_t dbase = sb + SBUF0 + (1 - buf) * SBUFSZ;
            const size_t gofs = (size_t)(t + 1) * 64 * 128;
            #pragma unroll
            for (int i = 0; i < 4; i++) {
                int idx = i * 256 + tid;
                int arr = idx >> 9, rem = idx & 511;
                int row = rem >> 3, ch = rem & 7;
                cp16(dbase + arr * STILE + row * APB + ch * 16,
                     src[arr] + gofs + (size_t)row * 128 + ch * 16);
            }
            CP_COMMIT();
        }

        const uint32_t sK = sb + SBUF0 + buf * SBUFSZ;
        const uint32_t sV = sK + STILE;

        // ---- S = QK^T (single-pass fp16; log2 units)
        float s[8][4];
        #pragma unroll
        for (int f = 0; f < 8; f++)
            #pragma unroll
            for (int e = 0; e < 4; e++) s[f][e] = 0.f;

        #pragma unroll
        for (int ks = 0; ks < 4; ks++) {
            #pragma unroll
            for (int p = 0; p < 4; p++) {
                uint32_t k0, k1, k2, k3;
                LDMATRIX_X4(k0, k1, k2, k3, sK + (16 * p) * APB + rowsel + ks * 32);
                mma16816h(s[2*p],   qf[ks][0], qf[ks][1], qf[ks][2], qf[ks][3], k0, k2);
                mma16816h(s[2*p+1], qf[ks][0], qf[ks][1], qf[ks][2], qf[ks][3], k1, k3);
            }
        }

        // ---- online softmax (log2 domain, f16x2 exp)
        float mxA = -1e30f, mxB = -1e30f;
        #pragma unroll
        for (int f = 0; f < 8; f++) {
            mxA = fmaxf(mxA, fmaxf(s[f][0], s[f][1]));
            mxB = fmaxf(mxB, fmaxf(s[f][2], s[f][3]));
        }
        mxA = fmaxf(mxA, __shfl_xor_sync(0xffffffffu, mxA, 1, 4));
        mxA = fmaxf(mxA, __shfl_xor_sync(0xffffffffu, mxA, 2, 4));
        mxB = fmaxf(mxB, __shfl_xor_sync(0xffffffffu, mxB, 1, 4));
        mxB = fmaxf(mxB, __shfl_xor_sync(0xffffffffu, mxB, 2, 4));
        float mnA = fmaxf(mA, mxA), mnB = fmaxf(mB, mxB);
        float alA = exp2f(mA - mnA), alB = exp2f(mB - mnB);
        mA = mnA; mB = mnB;

        uint32_t pp[8][2];
        #pragma unroll
        for (int f = 0; f < 8; f++) {
            CVT_F16X2(pp[f][0], s[f][0] - mnA, s[f][1] - mnA);
            EX2_F16X2(pp[f][0]);
            CVT_F16X2(pp[f][1], s[f][2] - mnB, s[f][3] - mnB);
            EX2_F16X2(pp[f][1]);
        }

        #pragma unroll
        for (int g = 0; g < 8; g++) {
            o[g][0] *= alA; o[g][1] *= alA;
            o[g][2] *= alB; o[g][3] *= alB;
        }
        ol[0] *= alA; ol[1] *= alA; ol[2] *= alB; ol[3] *= alB;

        // ---- O += P @ V ; l += P @ 1 (constant ones fragment)
        #pragma unroll
        for (int kt = 0; kt < 4; kt++) {
            uint32_t a0 = pp[2*kt][0], a1 = pp[2*kt][1];
            uint32_t a2 = pp[2*kt+1][0], a3 = pp[2*kt+1][1];
            #pragma unroll
            for (int g = 0; g < 4; g++) {
                uint32_t v0, v1, v2, v3;
                LDMATRIX_X4_T(v0, v1, v2, v3, sV + (16 * kt) * APB + rowsel + g * 32);
                mma16816h(o[2*g],   a0, a1, a2, a3, v0, v1);
                mma16816h(o[2*g+1], a0, a1, a2, a3, v2, v3);
            }
            mma16816h(ol, a0, a1, a2, a3, ONES2, ONES2);
        }
    }

    // ---- normalize + write fp16 [B,N,C]
    const float ivA = 1.f / ol[0], ivB = 1.f / ol[2];
    const int rowA = q0 + wq + (lane >> 2);
    const int col0 = h * D_ + 2 * (lane & 3);
    #pragma unroll
    for (int g = 0; g < 8; g++) {
        uint32_t vp;
        CVT_F16X2(vp, o[g][0] * ivA, o[g][1] * ivA);
        size_t e = (size_t)(b * N_ + rowA) * C_ + col0 + 8 * g;
        *(uint32_t*)((char*)px + e * 2) = vp;

        CVT_F16X2(vp, o[g][2] * ivB, o[g][3] * ivB);
        e = (size_t)(b * N_ + rowA + 8) * C_ + col0 + 8 * g;
        *(uint32_t*)((char*)px + e * 2) = vp;
    }
}

extern "C" void kernel_launch(void* const* d_in, const int* in_sizes, int n_in,
                              void* d_out, int out_size)
{
    const float* query = (const float*)d_in[0];
    const float* key   = (const float*)d_in[1];
    const float* value = (const float*)d_in[2];
    const float* Wq    = (const float*)d_in[3];
    const float* Wk    = (const float*)d_in[4];
    const float* bk    = (const float*)d_in[5];
    const float* Wv    = (const float*)d_in[6];
    const float* Wp    = (const float*)d_in[7];
    const float* bp    = (const float*)d_in[8];
    float* out = (float*)d_out;

    #define GA(sym) ({ void* _p; cudaGetSymbolAddress(&_p, sym); _p; })
    __half *iq = (__half*)GA(g_iq), *ik = (__half*)GA(g_ik), *iv = (__half*)GA(g_iv);
    __half *wq = (__half*)GA(g_wq), *wk = (__half*)GA(g_wk), *wv = (__half*)GA(g_wv);
    __half *wph = (__half*)GA(g_wph), *wpl = (__half*)GA(g_wpl);
    __half *pq = (__half*)GA(g_q16), *pk = (__half*)GA(g_k16), *pv = (__half*)GA(g_v16);
    __half *px = (__half*)GA(g_x16);

    static bool attr_done = false;
    if (!attr_done) {
        cudaFuncSetAttribute(projP, cudaFuncAttributeMaxDynamicSharedMemorySize, PROJP_SMEM);
        cudaFuncSetAttribute(attn_mma, cudaFuncAttributeMaxDynamicSharedMemorySize, ATT_SMEM);
        attr_done = true;
    }

    const int nx4 = M_ * C_ / 4;
    const int nw4 = C_ * C_ / 4;
    cvt3<<<dim3((nx4 + 255) / 256, 3), 256>>>(
        (const float4*)query, (const float4*)key, (const float4*)value,
        (uint2*)iq, (uint2*)ik, (uint2*)iv, nx4);
    cvt3<<<dim3((nw4 + 255) / 256, 3), 256>>>(
        (const float4*)Wq, (const float4*)Wk, (const float4*)Wv,
        (uint2*)wq, (uint2*)wk, (uint2*)wv, nw4);
    split_h<<<(nw4 + 255) / 256, 256>>>((const float4*)Wp, (uint2*)wph, (uint2*)wpl, nw4);

    projQKV<<<dim3(6, 64, 3), 256>>>(iq, ik, iv, wq, wk, wv, bk, pq, pk, pv);

    attn_mma<<<dim3(32, 24), 256, ATT_SMEM>>>(px);

    projP<<<dim3(6, 64), 256, PROJP_SMEM>>>(px, wph, wpl, bp, out);
}